// round 2
// baseline (speedup 1.0000x reference)
#include <cuda_runtime.h>

// Problem constants
#define BB  2
#define SS  2048
#define DD  1024
#define HH  16
#define DHH 64
#define MM  (BB*SS)    // 4096
#define BHH (BB*HH)    // 32

// Scratch (device globals; no allocation allowed in kernel_launch)
__device__ float g_q[(size_t)BHH*SS*DHH];      // [B,H,S,DH]
__device__ float g_k[(size_t)BHH*SS*DHH];
__device__ float g_v[(size_t)BHH*SS*DHH];
__device__ float g_attn[(size_t)BHH*SS*SS];    // [B,H,S,S] 512MB
__device__ float g_ctx[(size_t)MM*DD];         // [B*S, D]
__device__ int   g_maskmode;                   // 1 = int32 mask, 0 = uint8 mask

// ---------------------------------------------------------------------------
// Detect mask element width. jnp bool likely converted to int32 by harness.
// If any of the first 8192 words is > 1, buffer must be byte-packed bools.
// ---------------------------------------------------------------------------
__global__ void detect_mask_kernel(const unsigned int* __restrict__ m) {
    __shared__ int bad;
    if (threadIdx.x == 0) bad = 0;
    __syncthreads();
    int local = 0;
    for (int i = threadIdx.x; i < 8192; i += 256)
        if (m[i] > 1u) local = 1;
    if (local) atomicOr(&bad, 1);
    __syncthreads();
    if (threadIdx.x == 0) g_maskmode = bad ? 0 : 1;
}

// ---------------------------------------------------------------------------
// NT GEMM: C[M,N] = (A[M,K] @ B[N,K]^T + bias[N]) * scale
// shaped=1: write to [B,H,S,DH] layout (m = b*S+s, n = h*DH+dh)
// 64x64 block tile, 4x4 per thread, 256 threads, BK=16
// ---------------------------------------------------------------------------
__global__ __launch_bounds__(256) void gemm_nt(
    const float* __restrict__ A, const float* __restrict__ Bm,
    const float* __restrict__ bias, float* __restrict__ C,
    int M, int N, int K, float scale, int shaped)
{
    __shared__ float As[16][68];   // [k][m]
    __shared__ float Bs[16][68];   // [k][n]
    const int tid = threadIdx.x;
    const int m0 = blockIdx.y * 64;
    const int n0 = blockIdx.x * 64;
    const int tx = tid & 15, ty = tid >> 4;
    const int lr = tid >> 2;            // 0..63
    const int lc = (tid & 3) << 2;      // 0,4,8,12

    float acc[4][4] = {};
    const float* Ab = A  + (size_t)(m0 + lr) * K + lc;
    const float* Bb = Bm + (size_t)(n0 + lr) * K + lc;

    for (int k0 = 0; k0 < K; k0 += 16) {
        float4 a = *(const float4*)(Ab + k0);
        float4 b = *(const float4*)(Bb + k0);
        As[lc+0][lr]=a.x; As[lc+1][lr]=a.y; As[lc+2][lr]=a.z; As[lc+3][lr]=a.w;
        Bs[lc+0][lr]=b.x; Bs[lc+1][lr]=b.y; Bs[lc+2][lr]=b.z; Bs[lc+3][lr]=b.w;
        __syncthreads();
#pragma unroll
        for (int kk = 0; kk < 16; kk++) {
            float4 ra = *(const float4*)&As[kk][ty<<2];
            float4 rb = *(const float4*)&Bs[kk][tx<<2];
            float pa[4] = {ra.x,ra.y,ra.z,ra.w};
            float pb[4] = {rb.x,rb.y,rb.z,rb.w};
#pragma unroll
            for (int i=0;i<4;i++)
#pragma unroll
                for (int j=0;j<4;j++)
                    acc[i][j] = fmaf(pa[i], pb[j], acc[i][j]);
        }
        __syncthreads();
    }

#pragma unroll
    for (int i=0;i<4;i++) {
        int m = m0 + (ty<<2) + i;
#pragma unroll
        for (int j=0;j<4;j++) {
            int n = n0 + (tx<<2) + j;
            float val = (acc[i][j] + bias[n]) * scale;
            if (shaped) {
                int b = m / SS, s = m % SS;
                int h = n / DHH, dh = n % DHH;
                C[(((size_t)b*HH + h)*SS + s)*DHH + dh] = val;
            } else {
                C[(size_t)m * N + n] = val;
            }
        }
    }
}

// ---------------------------------------------------------------------------
// scores[bh, qi, ki] = sum_d q[bh,qi,d]*k[bh,ki,d]; masked -> -1e18
// 64x64 tile, full K=64 in smem
// ---------------------------------------------------------------------------
__global__ __launch_bounds__(256) void scores_kernel(
    const float* __restrict__ q, const float* __restrict__ k,
    const char* __restrict__ mask, float* __restrict__ scores)
{
    __shared__ float Qs[64][68];   // [k][m]
    __shared__ float Ks[64][68];   // [k][n]
    const int bh = blockIdx.z;
    const int b  = bh / HH;
    const int qi0 = blockIdx.y * 64;
    const int ki0 = blockIdx.x * 64;
    const float* qb = q + (size_t)bh * SS * DHH;
    const float* kb = k + (size_t)bh * SS * DHH;
    const int tid = threadIdx.x;
    const int tx = tid & 15, ty = tid >> 4;
    const int mode = g_maskmode;   // 1=int32, 0=uint8

#pragma unroll
    for (int it = 0; it < 4; it++) {
        int l = tid + 256*it;
        int r = l >> 4;              // 0..63
        int c = (l & 15) << 2;       // 0..60
        float4 a = *(const float4*)(qb + (size_t)(qi0 + r)*DHH + c);
        Qs[c+0][r]=a.x; Qs[c+1][r]=a.y; Qs[c+2][r]=a.z; Qs[c+3][r]=a.w;
        float4 v = *(const float4*)(kb + (size_t)(ki0 + r)*DHH + c);
        Ks[c+0][r]=v.x; Ks[c+1][r]=v.y; Ks[c+2][r]=v.z; Ks[c+3][r]=v.w;
    }
    __syncthreads();

    float acc[4][4] = {};
#pragma unroll 16
    for (int kk = 0; kk < 64; kk++) {
        float4 ra = *(const float4*)&Qs[kk][ty<<2];
        float4 rb = *(const float4*)&Ks[kk][tx<<2];
        float pa[4] = {ra.x,ra.y,ra.z,ra.w};
        float pb[4] = {rb.x,rb.y,rb.z,rb.w};
#pragma unroll
        for (int i=0;i<4;i++)
#pragma unroll
            for (int j=0;j<4;j++)
                acc[i][j] = fmaf(pa[i], pb[j], acc[i][j]);
    }

    float* sb = scores + (size_t)bh * SS * SS;
#pragma unroll
    for (int i=0;i<4;i++) {
        int qi = qi0 + (ty<<2) + i;
#pragma unroll
        for (int j=0;j<4;j++) {
            int ki = ki0 + (tx<<2) + j;
            size_t midx = (size_t)b*SS*SS + (size_t)qi*SS + ki;
            int mval = mode ? ((const int*)mask)[midx]
                            : (int)((const unsigned char*)mask)[midx];
            float val = mval ? -1e18f : acc[i][j];
            sb[(size_t)qi*SS + ki] = val;
        }
    }
}

// ---------------------------------------------------------------------------
// In-place softmax over rows of length S=2048; head 0 also written to topattn
// One block (256 threads) per row.
// ---------------------------------------------------------------------------
__global__ __launch_bounds__(256) void softmax_kernel(
    float* __restrict__ scores, float* __restrict__ topattn)
{
    const int r = blockIdx.x;              // (b*H + h)*S + qi
    float* row = scores + (size_t)r * SS;
    const int tid = threadIdx.x;
    __shared__ float red[256];

    float vals[8];
    float lmax = -3.4e38f;
#pragma unroll
    for (int i=0;i<8;i++) { vals[i] = row[tid + 256*i]; lmax = fmaxf(lmax, vals[i]); }
    red[tid] = lmax; __syncthreads();
    for (int s=128; s>0; s>>=1) { if (tid < s) red[tid] = fmaxf(red[tid], red[tid+s]); __syncthreads(); }
    float m = red[0]; __syncthreads();

    float lsum = 0.f;
#pragma unroll
    for (int i=0;i<8;i++) { vals[i] = __expf(vals[i] - m); lsum += vals[i]; }
    red[tid] = lsum; __syncthreads();
    for (int s=128; s>0; s>>=1) { if (tid < s) red[tid] += red[tid+s]; __syncthreads(); }
    float inv = 1.0f / red[0];

    const int h  = (r / SS) % HH;
    const int b  = r / (SS * HH);
    const int qi = r % SS;
    float* tp = topattn + ((size_t)b*SS + qi) * SS;
#pragma unroll
    for (int i=0;i<8;i++) {
        float v = vals[i] * inv;
        row[tid + 256*i] = v;
        if (h == 0) tp[tid + 256*i] = v;
    }
}

// ---------------------------------------------------------------------------
// ctx[b, s, h*DH + n] = sum_k attn[bh, s, k] * v[bh, k, n]
// 64 rows x 64 cols (full DH) per block, BK=32
// ---------------------------------------------------------------------------
__global__ __launch_bounds__(256) void ctx_kernel(
    const float* __restrict__ attn, const float* __restrict__ v,
    float* __restrict__ ctx)
{
    __shared__ float As[32][68];   // [k][m]
    __shared__ float Bs[32][68];   // [k][n]
    const int m0 = blockIdx.x * 64;
    const int bh = blockIdx.y;
    const int b = bh / HH, h = bh % HH;
    const float* ab = attn + (size_t)bh * SS * SS;
    const float* vb = v    + (size_t)bh * SS * DHH;
    const int tid = threadIdx.x;
    const int tx = tid & 15, ty = tid >> 4;

    float acc[4][4] = {};
    for (int k0 = 0; k0 < SS; k0 += 32) {
#pragma unroll
        for (int it = 0; it < 2; it++) {
            int l = tid + 256*it;
            int r = l >> 3;            // 0..63
            int c = (l & 7) << 2;      // 0..28
            float4 a = *(const float4*)(ab + (size_t)(m0 + r)*SS + k0 + c);
            As[c+0][r]=a.x; As[c+1][r]=a.y; As[c+2][r]=a.z; As[c+3][r]=a.w;
        }
#pragma unroll
        for (int it = 0; it < 2; it++) {
            int l = tid + 256*it;
            int r = l >> 4;            // 0..31
            int c = (l & 15) << 2;     // 0..60
            float4 bv4 = *(const float4*)(vb + (size_t)(k0 + r)*DHH + c);
            *(float4*)&Bs[r][c] = bv4;
        }
        __syncthreads();
#pragma unroll
        for (int kk = 0; kk < 32; kk++) {
            float4 ra = *(const float4*)&As[kk][ty<<2];
            float4 rb = *(const float4*)&Bs[kk][tx<<2];
            float pa[4] = {ra.x,ra.y,ra.z,ra.w};
            float pb[4] = {rb.x,rb.y,rb.z,rb.w};
#pragma unroll
            for (int i=0;i<4;i++)
#pragma unroll
                for (int j=0;j<4;j++)
                    acc[i][j] = fmaf(pa[i], pb[j], acc[i][j]);
        }
        __syncthreads();
    }

#pragma unroll
    for (int i=0;i<4;i++) {
        int m = m0 + (ty<<2) + i;
#pragma unroll
        for (int j=0;j<4;j++) {
            int n = (tx<<2) + j;
            ctx[((size_t)(b*SS + m))*DD + h*DHH + n] = acc[i][j];
        }
    }
}

// ---------------------------------------------------------------------------
extern "C" void kernel_launch(void* const* d_in, const int* in_sizes, int n_in,
                              void* d_out, int out_size)
{
    const float* key   = (const float*)d_in[0];
    const float* value = (const float*)d_in[1];
    const float* query = (const float*)d_in[2];
    const char*  mask  = (const char*)d_in[3];
    const float* Wk = (const float*)d_in[4];
    const float* bk = (const float*)d_in[5];
    const float* Wv = (const float*)d_in[6];
    const float* bv = (const float*)d_in[7];
    const float* Wq = (const float*)d_in[8];
    const float* bq = (const float*)d_in[9];
    const float* Wo = (const float*)d_in[10];
    const float* bo = (const float*)d_in[11];
    float* out = (float*)d_out;

    float *q, *k, *v, *attn, *ctx;
    cudaGetSymbolAddress((void**)&q,    g_q);
    cudaGetSymbolAddress((void**)&k,    g_k);
    cudaGetSymbolAddress((void**)&v,    g_v);
    cudaGetSymbolAddress((void**)&attn, g_attn);
    cudaGetSymbolAddress((void**)&ctx,  g_ctx);

    detect_mask_kernel<<<1, 256>>>((const unsigned int*)mask);

    dim3 gproj(DD/64, MM/64);           // (16, 64)
    gemm_nt<<<gproj, 256>>>(key,   Wk, bk, k, MM, DD, DD, 1.0f,   1);
    gemm_nt<<<gproj, 256>>>(value, Wv, bv, v, MM, DD, DD, 1.0f,   1);
    gemm_nt<<<gproj, 256>>>(query, Wq, bq, q, MM, DD, DD, 0.125f, 1);

    dim3 gsc(SS/64, SS/64, BHH);        // (32, 32, 32)
    scores_kernel<<<gsc, 256>>>(q, k, mask, attn);

    softmax_kernel<<<BHH*SS, 256>>>(attn, out + (size_t)MM*DD);

    dim3 gctx(SS/64, BHH);              // (32, 32)
    ctx_kernel<<<gctx, 256>>>(attn, v, ctx);

    gemm_nt<<<gproj, 256>>>(ctx, Wo, bo, out, MM, DD, DD, 1.0f, 0);
}

// round 4
// speedup vs baseline: 1.3491x; 1.3491x over previous
#include <cuda_runtime.h>
#include <cuda_bf16.h>
#include <cstdint>

// Problem constants
#define BB  2
#define SS  2048
#define DD  1024
#define HH  16
#define DHH 64
#define MM  (BB*SS)    // 4096
#define BHH (BB*HH)    // 32

// ---------------------------------------------------------------------------
// Scratch (device globals)
// ---------------------------------------------------------------------------
__device__ float g_q[(size_t)BHH*SS*DHH];
__device__ float g_k[(size_t)BHH*SS*DHH];
__device__ float g_v[(size_t)BHH*SS*DHH];
__device__ float g_attn[(size_t)BHH*SS*SS];    // 512MB
__device__ float g_ctx[(size_t)MM*DD];
__device__ int   g_maskmode;

// bf16 hi/lo split buffers
__device__ __nv_bfloat16 g_key_hi[(size_t)MM*DD],  g_key_lo[(size_t)MM*DD];
__device__ __nv_bfloat16 g_val_hi[(size_t)MM*DD],  g_val_lo[(size_t)MM*DD];
__device__ __nv_bfloat16 g_qry_hi[(size_t)MM*DD],  g_qry_lo[(size_t)MM*DD];
__device__ __nv_bfloat16 g_ctx_hi[(size_t)MM*DD],  g_ctx_lo[(size_t)MM*DD];
__device__ __nv_bfloat16 g_wk_hi[(size_t)DD*DD],   g_wk_lo[(size_t)DD*DD];
__device__ __nv_bfloat16 g_wv_hi[(size_t)DD*DD],   g_wv_lo[(size_t)DD*DD];
__device__ __nv_bfloat16 g_wq_hi[(size_t)DD*DD],   g_wq_lo[(size_t)DD*DD];
__device__ __nv_bfloat16 g_wo_hi[(size_t)DD*DD],   g_wo_lo[(size_t)DD*DD];

// ---------------------------------------------------------------------------
// Helpers (portable PTX only: ldmatrix / mma.sync / cp.async)
// ---------------------------------------------------------------------------
__device__ __forceinline__ uint32_t smem_u32(const void* p) {
    uint32_t a;
    asm("{ .reg .u64 t; cvta.to.shared.u64 t, %1; cvt.u32.u64 %0, t; }" : "=r"(a) : "l"(p));
    return a;
}
__device__ __forceinline__ void cp_async16(uint32_t saddr, const void* gaddr) {
    asm volatile("cp.async.cg.shared.global [%0], [%1], 16;" :: "r"(saddr), "l"(gaddr));
}
__device__ __forceinline__ void cp_commit() { asm volatile("cp.async.commit_group;"); }
template <int N>
__device__ __forceinline__ void cp_wait() { asm volatile("cp.async.wait_group %0;" :: "n"(N)); }

__device__ __forceinline__ void ldm_x4(uint32_t* r, uint32_t addr) {
    asm volatile("ldmatrix.sync.aligned.m8n8.x4.shared.b16 {%0,%1,%2,%3}, [%4];"
        : "=r"(r[0]), "=r"(r[1]), "=r"(r[2]), "=r"(r[3]) : "r"(addr));
}
__device__ __forceinline__ void ldm_x2(uint32_t* r, uint32_t addr) {
    asm volatile("ldmatrix.sync.aligned.m8n8.x2.shared.b16 {%0,%1}, [%2];"
        : "=r"(r[0]), "=r"(r[1]) : "r"(addr));
}
__device__ __forceinline__ void mma_bf16(float* c, const uint32_t* a, const uint32_t* b) {
    asm volatile("mma.sync.aligned.m16n8k16.row.col.f32.bf16.bf16.f32 "
        "{%0,%1,%2,%3}, {%4,%5,%6,%7}, {%8,%9}, {%0,%1,%2,%3};"
        : "+f"(c[0]), "+f"(c[1]), "+f"(c[2]), "+f"(c[3])
        : "r"(a[0]), "r"(a[1]), "r"(a[2]), "r"(a[3]), "r"(b[0]), "r"(b[1]));
}

// ---------------------------------------------------------------------------
// Split fp32 -> bf16 hi + bf16 lo, vectorized x4
// ---------------------------------------------------------------------------
__global__ __launch_bounds__(256) void split_kernel(
    const float* __restrict__ x, __nv_bfloat16* __restrict__ hi,
    __nv_bfloat16* __restrict__ lo, int n4)
{
    int i = blockIdx.x * 256 + threadIdx.x;
    if (i >= n4) return;
    float4 f = ((const float4*)x)[i];
    __nv_bfloat16 h0 = __float2bfloat16(f.x), h1 = __float2bfloat16(f.y);
    __nv_bfloat16 h2 = __float2bfloat16(f.z), h3 = __float2bfloat16(f.w);
    __nv_bfloat16 l0 = __float2bfloat16(f.x - __bfloat162float(h0));
    __nv_bfloat16 l1 = __float2bfloat16(f.y - __bfloat162float(h1));
    __nv_bfloat16 l2 = __float2bfloat16(f.z - __bfloat162float(h2));
    __nv_bfloat16 l3 = __float2bfloat16(f.w - __bfloat162float(h3));
    __nv_bfloat162* hp = (__nv_bfloat162*)hi;
    __nv_bfloat162* lp = (__nv_bfloat162*)lo;
    hp[2*i]   = __nv_bfloat162(h0, h1);
    hp[2*i+1] = __nv_bfloat162(h2, h3);
    lp[2*i]   = __nv_bfloat162(l0, l1);
    lp[2*i+1] = __nv_bfloat162(l2, l3);
}

// ---------------------------------------------------------------------------
// Mask dtype detection (int32 vs uint8)
// ---------------------------------------------------------------------------
__global__ void detect_mask_kernel(const unsigned int* __restrict__ m) {
    __shared__ int bad;
    if (threadIdx.x == 0) bad = 0;
    __syncthreads();
    int local = 0;
    for (int i = threadIdx.x; i < 8192; i += 256)
        if (m[i] > 1u) local = 1;
    if (local) atomicOr(&bad, 1);
    __syncthreads();
    if (threadIdx.x == 0) g_maskmode = bad ? 0 : 1;
}

// ---------------------------------------------------------------------------
// mma.sync split-bf16 GEMM: C[4096,1024] = A @ W^T + bias (then *scale)
// 128x128 CTA tile, 8 warps (2x4), warp tile 64x32, BK=32, cp.async 2-stage.
// ---------------------------------------------------------------------------
#define RS 40                            // padded row stride (bf16 elems)
#define TILE_B (128*RS*2)                // 10240 bytes per tile
#define BUF_B  (4*TILE_B)                // Ahi|Alo|Whi|Wlo = 40960
#define GSMEM  (2*BUF_B)                 // 81920

__global__ __launch_bounds__(256) void gemm_mma(
    const __nv_bfloat16* __restrict__ Ahi, const __nv_bfloat16* __restrict__ Alo,
    const __nv_bfloat16* __restrict__ Whi, const __nv_bfloat16* __restrict__ Wlo,
    const float* __restrict__ bias, float* __restrict__ C, float scale, int shaped)
{
    extern __shared__ char smem[];
    const int tid  = threadIdx.x;
    const int wid  = tid >> 5, lane = tid & 31;
    const int warp_m = wid & 1, warp_n = wid >> 1;
    const int m0 = blockIdx.y * 128, n0 = blockIdx.x * 128;

    const __nv_bfloat16* srcs[4] = {
        Ahi + (size_t)m0 * DD, Alo + (size_t)m0 * DD,
        Whi + (size_t)n0 * DD, Wlo + (size_t)n0 * DD };

    auto load_chunk = [&](int chunk, int buf) {
        char* sb = smem + buf * BUF_B;
#pragma unroll
        for (int t = 0; t < 4; t++) {
            const __nv_bfloat16* src = srcs[t] + chunk * 32;
            char* dst = sb + t * TILE_B;
#pragma unroll
            for (int it = 0; it < 2; it++) {
                int i = tid + 256 * it;          // 0..511
                int r = i >> 2, seg = i & 3;
                cp_async16(smem_u32(dst + r * (RS*2) + seg * 16),
                           src + (size_t)r * DD + seg * 8);
            }
        }
        cp_commit();
    };

    float acc[4][4][4] = {};

    load_chunk(0, 0);
    for (int chunk = 0; chunk < 32; chunk++) {
        const int buf = chunk & 1;
        if (chunk + 1 < 32) { load_chunk(chunk + 1, buf ^ 1); cp_wait<1>(); }
        else                { cp_wait<0>(); }
        __syncthreads();

        char* sb = smem + buf * BUF_B;
        const uint32_t aHiB = smem_u32(sb);
        const uint32_t aLoB = aHiB + TILE_B;
        const uint32_t bHiB = aHiB + 2*TILE_B;
        const uint32_t bLoB = aHiB + 3*TILE_B;

#pragma unroll
        for (int ks = 0; ks < 2; ks++) {
            const int k0 = ks * 16;
            uint32_t ahi[4][4], alo[4][4], bhi[4][2], blo[4][2];
            // A fragments: rows warp_m*64 + ma*16 + lane%16, col-half lane/16
            {
                const int lr = lane & 15;
                const int ch = (lane >> 4) << 3;
#pragma unroll
                for (int ma = 0; ma < 4; ma++) {
                    uint32_t off = ((warp_m*64 + ma*16 + lr) * RS + k0 + ch) * 2;
                    ldm_x4(ahi[ma], aHiB + off);
                    ldm_x4(alo[ma], aLoB + off);
                }
            }
            // B fragments: rows warp_n*32 + na*8 + idx%8, k-half idx/8 (idx=lane%16)
            {
                const int idx = lane & 15;
                const int nr = idx & 7;
                const int kh = (idx >> 3) << 3;
#pragma unroll
                for (int na = 0; na < 4; na++) {
                    uint32_t off = ((warp_n*32 + na*8 + nr) * RS + k0 + kh) * 2;
                    ldm_x2(bhi[na], bHiB + off);
                    ldm_x2(blo[na], bLoB + off);
                }
            }
#pragma unroll
            for (int ma = 0; ma < 4; ma++)
#pragma unroll
                for (int na = 0; na < 4; na++) {
                    mma_bf16(acc[ma][na], ahi[ma], bhi[na]);
                    mma_bf16(acc[ma][na], ahi[ma], blo[na]);
                    mma_bf16(acc[ma][na], alo[ma], bhi[na]);
                }
        }
        __syncthreads();
    }

    // Epilogue
#pragma unroll
    for (int ma = 0; ma < 4; ma++) {
        const int r0 = m0 + warp_m*64 + ma*16 + (lane >> 2);
#pragma unroll
        for (int na = 0; na < 4; na++) {
            const int c0 = n0 + warp_n*32 + na*8 + (lane & 3)*2;
            const float bx = bias[c0], by = bias[c0+1];
#pragma unroll
            for (int half = 0; half < 2; half++) {
                const int m = r0 + half*8;
                float2 o;
                o.x = (acc[ma][na][half*2+0] + bx) * scale;
                o.y = (acc[ma][na][half*2+1] + by) * scale;
                if (shaped) {
                    int b = m >> 11, s = m & (SS-1);
                    int h = c0 >> 6, dh = c0 & 63;
                    *(float2*)&C[(((size_t)b*HH + h)*SS + s)*DHH + dh] = o;
                } else {
                    *(float2*)&C[(size_t)m * DD + c0] = o;
                }
            }
        }
    }
}

// ---------------------------------------------------------------------------
// scores[bh, qi, ki] = sum_d q*k; masked -> -1e18  (SIMT)
// ---------------------------------------------------------------------------
__global__ __launch_bounds__(256) void scores_kernel(
    const float* __restrict__ q, const float* __restrict__ k,
    const char* __restrict__ mask, float* __restrict__ scores)
{
    __shared__ float Qs[64][68];
    __shared__ float Ks[64][68];
    const int bh = blockIdx.z;
    const int b  = bh / HH;
    const int qi0 = blockIdx.y * 64;
    const int ki0 = blockIdx.x * 64;
    const float* qb = q + (size_t)bh * SS * DHH;
    const float* kb = k + (size_t)bh * SS * DHH;
    const int tid = threadIdx.x;
    const int tx = tid & 15, ty = tid >> 4;
    const int mode = g_maskmode;

#pragma unroll
    for (int it = 0; it < 4; it++) {
        int l = tid + 256*it;
        int r = l >> 4;
        int c = (l & 15) << 2;
        float4 a = *(const float4*)(qb + (size_t)(qi0 + r)*DHH + c);
        Qs[c+0][r]=a.x; Qs[c+1][r]=a.y; Qs[c+2][r]=a.z; Qs[c+3][r]=a.w;
        float4 v = *(const float4*)(kb + (size_t)(ki0 + r)*DHH + c);
        Ks[c+0][r]=v.x; Ks[c+1][r]=v.y; Ks[c+2][r]=v.z; Ks[c+3][r]=v.w;
    }
    __syncthreads();

    float acc[4][4] = {};
#pragma unroll 16
    for (int kk = 0; kk < 64; kk++) {
        float4 ra = *(const float4*)&Qs[kk][ty<<2];
        float4 rb = *(const float4*)&Ks[kk][tx<<2];
        float pa[4] = {ra.x,ra.y,ra.z,ra.w};
        float pb[4] = {rb.x,rb.y,rb.z,rb.w};
#pragma unroll
        for (int i=0;i<4;i++)
#pragma unroll
            for (int j=0;j<4;j++)
                acc[i][j] = fmaf(pa[i], pb[j], acc[i][j]);
    }

    float* sb = scores + (size_t)bh * SS * SS;
#pragma unroll
    for (int i=0;i<4;i++) {
        int qi = qi0 + (ty<<2) + i;
#pragma unroll
        for (int j=0;j<4;j++) {
            int ki = ki0 + (tx<<2) + j;
            size_t midx = (size_t)b*SS*SS + (size_t)qi*SS + ki;
            int mval = mode ? ((const int*)mask)[midx]
                            : (int)((const unsigned char*)mask)[midx];
            sb[(size_t)qi*SS + ki] = mval ? -1e18f : acc[i][j];
        }
    }
}

// ---------------------------------------------------------------------------
// softmax
// ---------------------------------------------------------------------------
__global__ __launch_bounds__(256) void softmax_kernel(
    float* __restrict__ scores, float* __restrict__ topattn)
{
    const int r = blockIdx.x;
    float* row = scores + (size_t)r * SS;
    const int tid = threadIdx.x;
    __shared__ float red[256];

    float vals[8];
    float lmax = -3.4e38f;
#pragma unroll
    for (int i=0;i<8;i++) { vals[i] = row[tid + 256*i]; lmax = fmaxf(lmax, vals[i]); }
    red[tid] = lmax; __syncthreads();
    for (int s=128; s>0; s>>=1) { if (tid < s) red[tid] = fmaxf(red[tid], red[tid+s]); __syncthreads(); }
    float m = red[0]; __syncthreads();

    float lsum = 0.f;
#pragma unroll
    for (int i=0;i<8;i++) { vals[i] = __expf(vals[i] - m); lsum += vals[i]; }
    red[tid] = lsum; __syncthreads();
    for (int s=128; s>0; s>>=1) { if (tid < s) red[tid] += red[tid+s]; __syncthreads(); }
    float inv = 1.0f / red[0];

    const int h  = (r / SS) % HH;
    const int b  = r / (SS * HH);
    const int qi = r % SS;
    float* tp = topattn + ((size_t)b*SS + qi) * SS;
#pragma unroll
    for (int i=0;i<8;i++) {
        float v = vals[i] * inv;
        row[tid + 256*i] = v;
        if (h == 0) tp[tid + 256*i] = v;
    }
}

// ---------------------------------------------------------------------------
// ctx (SIMT)
// ---------------------------------------------------------------------------
__global__ __launch_bounds__(256) void ctx_kernel(
    const float* __restrict__ attn, const float* __restrict__ v,
    float* __restrict__ ctx)
{
    __shared__ float As[32][68];
    __shared__ float Bs[32][68];
    const int m0 = blockIdx.x * 64;
    const int bh = blockIdx.y;
    const int b = bh / HH, h = bh % HH;
    const float* ab = attn + (size_t)bh * SS * SS;
    const float* vb = v    + (size_t)bh * SS * DHH;
    const int tid = threadIdx.x;
    const int tx = tid & 15, ty = tid >> 4;

    float acc[4][4] = {};
    for (int k0 = 0; k0 < SS; k0 += 32) {
#pragma unroll
        for (int it = 0; it < 2; it++) {
            int l = tid + 256*it;
            int r = l >> 3;
            int c = (l & 7) << 2;
            float4 a = *(const float4*)(ab + (size_t)(m0 + r)*SS + k0 + c);
            As[c+0][r]=a.x; As[c+1][r]=a.y; As[c+2][r]=a.z; As[c+3][r]=a.w;
        }
#pragma unroll
        for (int it = 0; it < 2; it++) {
            int l = tid + 256*it;
            int r = l >> 4;
            int c = (l & 15) << 2;
            float4 bv4 = *(const float4*)(vb + (size_t)(k0 + r)*DHH + c);
            *(float4*)&Bs[r][c] = bv4;
        }
        __syncthreads();
#pragma unroll
        for (int kk = 0; kk < 32; kk++) {
            float4 ra = *(const float4*)&As[kk][ty<<2];
            float4 rb = *(const float4*)&Bs[kk][tx<<2];
            float pa[4] = {ra.x,ra.y,ra.z,ra.w};
            float pb[4] = {rb.x,rb.y,rb.z,rb.w};
#pragma unroll
            for (int i=0;i<4;i++)
#pragma unroll
                for (int j=0;j<4;j++)
                    acc[i][j] = fmaf(pa[i], pb[j], acc[i][j]);
        }
        __syncthreads();
    }

#pragma unroll
    for (int i=0;i<4;i++) {
        int m = m0 + (ty<<2) + i;
#pragma unroll
        for (int j=0;j<4;j++) {
            int n = (tx<<2) + j;
            ctx[((size_t)(b*SS + m))*DD + h*DHH + n] = acc[i][j];
        }
    }
}

// ---------------------------------------------------------------------------
extern "C" void kernel_launch(void* const* d_in, const int* in_sizes, int n_in,
                              void* d_out, int out_size)
{
    const float* key   = (const float*)d_in[0];
    const float* value = (const float*)d_in[1];
    const float* query = (const float*)d_in[2];
    const char*  mask  = (const char*)d_in[3];
    const float* Wk = (const float*)d_in[4];
    const float* bk = (const float*)d_in[5];
    const float* Wv = (const float*)d_in[6];
    const float* bv = (const float*)d_in[7];
    const float* Wq = (const float*)d_in[8];
    const float* bq = (const float*)d_in[9];
    const float* Wo = (const float*)d_in[10];
    const float* bo = (const float*)d_in[11];
    float* out = (float*)d_out;

    float *q, *k, *v, *attn, *ctx;
    cudaGetSymbolAddress((void**)&q,    g_q);
    cudaGetSymbolAddress((void**)&k,    g_k);
    cudaGetSymbolAddress((void**)&v,    g_v);
    cudaGetSymbolAddress((void**)&attn, g_attn);
    cudaGetSymbolAddress((void**)&ctx,  g_ctx);

    __nv_bfloat16 *keyh,*keyl,*valh,*vall,*qryh,*qryl,*ctxh,*ctxl;
    __nv_bfloat16 *wkh,*wkl,*wvh,*wvl,*wqh,*wql,*woh,*wol;
    cudaGetSymbolAddress((void**)&keyh, g_key_hi); cudaGetSymbolAddress((void**)&keyl, g_key_lo);
    cudaGetSymbolAddress((void**)&valh, g_val_hi); cudaGetSymbolAddress((void**)&vall, g_val_lo);
    cudaGetSymbolAddress((void**)&qryh, g_qry_hi); cudaGetSymbolAddress((void**)&qryl, g_qry_lo);
    cudaGetSymbolAddress((void**)&ctxh, g_ctx_hi); cudaGetSymbolAddress((void**)&ctxl, g_ctx_lo);
    cudaGetSymbolAddress((void**)&wkh,  g_wk_hi);  cudaGetSymbolAddress((void**)&wkl,  g_wk_lo);
    cudaGetSymbolAddress((void**)&wvh,  g_wv_hi);  cudaGetSymbolAddress((void**)&wvl,  g_wv_lo);
    cudaGetSymbolAddress((void**)&wqh,  g_wq_hi);  cudaGetSymbolAddress((void**)&wql,  g_wq_lo);
    cudaGetSymbolAddress((void**)&woh,  g_wo_hi);  cudaGetSymbolAddress((void**)&wol,  g_wo_lo);

    cudaFuncSetAttribute(gemm_mma, cudaFuncAttributeMaxDynamicSharedMemorySize, GSMEM);

    detect_mask_kernel<<<1, 256>>>((const unsigned int*)mask);

    const int nIn4 = MM*DD/4, nW4 = DD*DD/4;
    split_kernel<<<nIn4/256, 256>>>(key,   keyh, keyl, nIn4);
    split_kernel<<<nIn4/256, 256>>>(value, valh, vall, nIn4);
    split_kernel<<<nIn4/256, 256>>>(query, qryh, qryl, nIn4);
    split_kernel<<<nW4/256, 256>>>(Wk, wkh, wkl, nW4);
    split_kernel<<<nW4/256, 256>>>(Wv, wvh, wvl, nW4);
    split_kernel<<<nW4/256, 256>>>(Wq, wqh, wql, nW4);
    split_kernel<<<nW4/256, 256>>>(Wo, woh, wol, nW4);

    dim3 gtc(DD/128, MM/128);   // (8, 32)
    gemm_mma<<<gtc, 256, GSMEM>>>(keyh, keyl, wkh, wkl, bk, k, 1.0f,   1);
    gemm_mma<<<gtc, 256, GSMEM>>>(valh, vall, wvh, wvl, bv, v, 1.0f,   1);
    gemm_mma<<<gtc, 256, GSMEM>>>(qryh, qryl, wqh, wql, bq, q, 0.125f, 1);

    dim3 gsc(SS/64, SS/64, BHH);
    scores_kernel<<<gsc, 256>>>(q, k, mask, attn);

    softmax_kernel<<<BHH*SS, 256>>>(attn, out + (size_t)MM*DD);

    dim3 gctx(SS/64, BHH);
    ctx_kernel<<<gctx, 256>>>(attn, v, ctx);

    split_kernel<<<nIn4/256, 256>>>(ctx, ctxh, ctxl, nIn4);
    gemm_mma<<<gtc, 256, GSMEM>>>(ctxh, ctxl, woh, wol, bo, out, 1.0f, 0);
}

// round 5
// speedup vs baseline: 2.7942x; 2.0711x over previous
#include <cuda_runtime.h>
#include <cuda_bf16.h>
#include <cstdint>

// Problem constants
#define BB  2
#define SS  2048
#define DD  1024
#define HH  16
#define DHH 64
#define MM  (BB*SS)    // 4096
#define BHH (BB*HH)    // 32

// ---------------------------------------------------------------------------
// Scratch (device globals)
// ---------------------------------------------------------------------------
__device__ float g_q[(size_t)BHH*SS*DHH];
__device__ float g_k[(size_t)BHH*SS*DHH];
__device__ float g_v[(size_t)BHH*SS*DHH];
__device__ float g_attn[(size_t)BB*SS*SS];     // head-0 scores only (32MB)
__device__ float g_ctx[(size_t)MM*DD];
__device__ int   g_maskmode;

// bf16 hi/lo split buffers
__device__ __nv_bfloat16 g_key_hi[(size_t)MM*DD],  g_key_lo[(size_t)MM*DD];
__device__ __nv_bfloat16 g_val_hi[(size_t)MM*DD],  g_val_lo[(size_t)MM*DD];
__device__ __nv_bfloat16 g_qry_hi[(size_t)MM*DD],  g_qry_lo[(size_t)MM*DD];
__device__ __nv_bfloat16 g_ctx_hi[(size_t)MM*DD],  g_ctx_lo[(size_t)MM*DD];
__device__ __nv_bfloat16 g_wk_hi[(size_t)DD*DD],   g_wk_lo[(size_t)DD*DD];
__device__ __nv_bfloat16 g_wv_hi[(size_t)DD*DD],   g_wv_lo[(size_t)DD*DD];
__device__ __nv_bfloat16 g_wq_hi[(size_t)DD*DD],   g_wq_lo[(size_t)DD*DD];
__device__ __nv_bfloat16 g_wo_hi[(size_t)DD*DD],   g_wo_lo[(size_t)DD*DD];
// attention operand splits
__device__ __nv_bfloat16 g_qs_hi[(size_t)BHH*SS*DHH], g_qs_lo[(size_t)BHH*SS*DHH];
__device__ __nv_bfloat16 g_ks_hi[(size_t)BHH*SS*DHH], g_ks_lo[(size_t)BHH*SS*DHH];
__device__ __nv_bfloat16 g_vt_hi[(size_t)BHH*DHH*SS], g_vt_lo[(size_t)BHH*DHH*SS]; // [bh][d][s]

// ---------------------------------------------------------------------------
// PTX helpers (portable: ldmatrix / mma.sync / cp.async)
// ---------------------------------------------------------------------------
__device__ __forceinline__ uint32_t smem_u32(const void* p) {
    uint32_t a;
    asm("{ .reg .u64 t; cvta.to.shared.u64 t, %1; cvt.u32.u64 %0, t; }" : "=r"(a) : "l"(p));
    return a;
}
__device__ __forceinline__ void cp_async16(uint32_t saddr, const void* gaddr) {
    asm volatile("cp.async.cg.shared.global [%0], [%1], 16;" :: "r"(saddr), "l"(gaddr));
}
__device__ __forceinline__ void cp_commit() { asm volatile("cp.async.commit_group;"); }
template <int N>
__device__ __forceinline__ void cp_wait() { asm volatile("cp.async.wait_group %0;" :: "n"(N)); }

__device__ __forceinline__ void ldm_x4(uint32_t* r, uint32_t addr) {
    asm volatile("ldmatrix.sync.aligned.m8n8.x4.shared.b16 {%0,%1,%2,%3}, [%4];"
        : "=r"(r[0]), "=r"(r[1]), "=r"(r[2]), "=r"(r[3]) : "r"(addr));
}
__device__ __forceinline__ void ldm_x2(uint32_t* r, uint32_t addr) {
    asm volatile("ldmatrix.sync.aligned.m8n8.x2.shared.b16 {%0,%1}, [%2];"
        : "=r"(r[0]), "=r"(r[1]) : "r"(addr));
}
__device__ __forceinline__ void mma_bf16(float* c, const uint32_t* a, const uint32_t* b) {
    asm volatile("mma.sync.aligned.m16n8k16.row.col.f32.bf16.bf16.f32 "
        "{%0,%1,%2,%3}, {%4,%5,%6,%7}, {%8,%9}, {%0,%1,%2,%3};"
        : "+f"(c[0]), "+f"(c[1]), "+f"(c[2]), "+f"(c[3])
        : "r"(a[0]), "r"(a[1]), "r"(a[2]), "r"(a[3]), "r"(b[0]), "r"(b[1]));
}

// ---------------------------------------------------------------------------
// Split fp32 -> bf16 hi + bf16 lo, vectorized x4
// ---------------------------------------------------------------------------
__global__ __launch_bounds__(256) void split_kernel(
    const float* __restrict__ x, __nv_bfloat16* __restrict__ hi,
    __nv_bfloat16* __restrict__ lo, int n4)
{
    int i = blockIdx.x * 256 + threadIdx.x;
    if (i >= n4) return;
    float4 f = ((const float4*)x)[i];
    __nv_bfloat16 h0 = __float2bfloat16(f.x), h1 = __float2bfloat16(f.y);
    __nv_bfloat16 h2 = __float2bfloat16(f.z), h3 = __float2bfloat16(f.w);
    __nv_bfloat16 l0 = __float2bfloat16(f.x - __bfloat162float(h0));
    __nv_bfloat16 l1 = __float2bfloat16(f.y - __bfloat162float(h1));
    __nv_bfloat16 l2 = __float2bfloat16(f.z - __bfloat162float(h2));
    __nv_bfloat16 l3 = __float2bfloat16(f.w - __bfloat162float(h3));
    __nv_bfloat162* hp = (__nv_bfloat162*)hi;
    __nv_bfloat162* lp = (__nv_bfloat162*)lo;
    hp[2*i]   = __nv_bfloat162(h0, h1);
    hp[2*i+1] = __nv_bfloat162(h2, h3);
    lp[2*i]   = __nv_bfloat162(l0, l1);
    lp[2*i+1] = __nv_bfloat162(l2, l3);
}

// ---------------------------------------------------------------------------
// Transpose+split V: v[bh][s][d] fp32 -> vt_hi/lo[bh][d][s] bf16
// ---------------------------------------------------------------------------
__global__ __launch_bounds__(256) void vt_split_kernel(
    const float* __restrict__ v, __nv_bfloat16* __restrict__ vth,
    __nv_bfloat16* __restrict__ vtl)
{
    __shared__ float t[64][65];
    const int bh = blockIdx.y, s0 = blockIdx.x * 64;
    const float* vb = v + ((size_t)bh*SS + s0)*DHH;
    const int tid = threadIdx.x;
#pragma unroll
    for (int it = 0; it < 4; it++) {
        int i = tid + it*256;
        int r = i >> 4, c4 = (i & 15) << 2;
        float4 x = *(const float4*)(vb + (size_t)r*DHH + c4);
        t[r][c4] = x.x; t[r][c4+1] = x.y; t[r][c4+2] = x.z; t[r][c4+3] = x.w;
    }
    __syncthreads();
#pragma unroll
    for (int it = 0; it < 4; it++) {
        int i = tid + it*256;
        int d = i >> 4, sseg = (i & 15) << 2;
        float x0 = t[sseg][d], x1 = t[sseg+1][d], x2 = t[sseg+2][d], x3 = t[sseg+3][d];
        __nv_bfloat16 h0 = __float2bfloat16(x0), h1 = __float2bfloat16(x1);
        __nv_bfloat16 h2 = __float2bfloat16(x2), h3 = __float2bfloat16(x3);
        __nv_bfloat16 e0 = __float2bfloat16(x0 - __bfloat162float(h0));
        __nv_bfloat16 e1 = __float2bfloat16(x1 - __bfloat162float(h1));
        __nv_bfloat16 e2 = __float2bfloat16(x2 - __bfloat162float(h2));
        __nv_bfloat16 e3 = __float2bfloat16(x3 - __bfloat162float(h3));
        size_t o = ((size_t)bh*DHH + d)*SS + s0 + sseg;
        ((__nv_bfloat162*)(vth + o))[0] = __nv_bfloat162(h0, h1);
        ((__nv_bfloat162*)(vth + o))[1] = __nv_bfloat162(h2, h3);
        ((__nv_bfloat162*)(vtl + o))[0] = __nv_bfloat162(e0, e1);
        ((__nv_bfloat162*)(vtl + o))[1] = __nv_bfloat162(e2, e3);
    }
}

// ---------------------------------------------------------------------------
// Mask dtype detection (int32 vs uint8)
// ---------------------------------------------------------------------------
__global__ void detect_mask_kernel(const unsigned int* __restrict__ m) {
    __shared__ int bad;
    if (threadIdx.x == 0) bad = 0;
    __syncthreads();
    int local = 0;
    for (int i = threadIdx.x; i < 8192; i += 256)
        if (m[i] > 1u) local = 1;
    if (local) atomicOr(&bad, 1);
    __syncthreads();
    if (threadIdx.x == 0) g_maskmode = bad ? 0 : 1;
}

// ---------------------------------------------------------------------------
// mma.sync split-bf16 GEMM (projections): C = A @ W^T + bias, *scale
// ---------------------------------------------------------------------------
#define RS 40
#define TILE_B (128*RS*2)
#define BUF_B  (4*TILE_B)
#define GSMEM  (2*BUF_B)

__global__ __launch_bounds__(256) void gemm_mma(
    const __nv_bfloat16* __restrict__ Ahi, const __nv_bfloat16* __restrict__ Alo,
    const __nv_bfloat16* __restrict__ Whi, const __nv_bfloat16* __restrict__ Wlo,
    const float* __restrict__ bias, float* __restrict__ C, float scale, int shaped)
{
    extern __shared__ char smem[];
    const int tid  = threadIdx.x;
    const int wid  = tid >> 5, lane = tid & 31;
    const int warp_m = wid & 1, warp_n = wid >> 1;
    const int m0 = blockIdx.y * 128, n0 = blockIdx.x * 128;

    const __nv_bfloat16* srcs[4] = {
        Ahi + (size_t)m0 * DD, Alo + (size_t)m0 * DD,
        Whi + (size_t)n0 * DD, Wlo + (size_t)n0 * DD };

    auto load_chunk = [&](int chunk, int buf) {
        char* sb = smem + buf * BUF_B;
#pragma unroll
        for (int t = 0; t < 4; t++) {
            const __nv_bfloat16* src = srcs[t] + chunk * 32;
            char* dst = sb + t * TILE_B;
#pragma unroll
            for (int it = 0; it < 2; it++) {
                int i = tid + 256 * it;
                int r = i >> 2, seg = i & 3;
                cp_async16(smem_u32(dst + r * (RS*2) + seg * 16),
                           src + (size_t)r * DD + seg * 8);
            }
        }
        cp_commit();
    };

    float acc[4][4][4] = {};

    load_chunk(0, 0);
    for (int chunk = 0; chunk < 32; chunk++) {
        const int buf = chunk & 1;
        if (chunk + 1 < 32) { load_chunk(chunk + 1, buf ^ 1); cp_wait<1>(); }
        else                { cp_wait<0>(); }
        __syncthreads();

        char* sb = smem + buf * BUF_B;
        const uint32_t aHiB = smem_u32(sb);
        const uint32_t aLoB = aHiB + TILE_B;
        const uint32_t bHiB = aHiB + 2*TILE_B;
        const uint32_t bLoB = aHiB + 3*TILE_B;

#pragma unroll
        for (int ks = 0; ks < 2; ks++) {
            const int k0 = ks * 16;
            uint32_t ahi[4][4], alo[4][4], bhi[4][2], blo[4][2];
            {
                const int lr = lane & 15;
                const int ch = (lane >> 4) << 3;
#pragma unroll
                for (int ma = 0; ma < 4; ma++) {
                    uint32_t off = ((warp_m*64 + ma*16 + lr) * RS + k0 + ch) * 2;
                    ldm_x4(ahi[ma], aHiB + off);
                    ldm_x4(alo[ma], aLoB + off);
                }
            }
            {
                const int idx = lane & 15;
                const int nr = idx & 7;
                const int kh = (idx >> 3) << 3;
#pragma unroll
                for (int na = 0; na < 4; na++) {
                    uint32_t off = ((warp_n*32 + na*8 + nr) * RS + k0 + kh) * 2;
                    ldm_x2(bhi[na], bHiB + off);
                    ldm_x2(blo[na], bLoB + off);
                }
            }
#pragma unroll
            for (int ma = 0; ma < 4; ma++)
#pragma unroll
                for (int na = 0; na < 4; na++) {
                    mma_bf16(acc[ma][na], ahi[ma], bhi[na]);
                    mma_bf16(acc[ma][na], ahi[ma], blo[na]);
                    mma_bf16(acc[ma][na], alo[ma], bhi[na]);
                }
        }
        __syncthreads();
    }

#pragma unroll
    for (int ma = 0; ma < 4; ma++) {
        const int r0 = m0 + warp_m*64 + ma*16 + (lane >> 2);
#pragma unroll
        for (int na = 0; na < 4; na++) {
            const int c0 = n0 + warp_n*32 + na*8 + (lane & 3)*2;
            const float bx = bias[c0], by = bias[c0+1];
#pragma unroll
            for (int half = 0; half < 2; half++) {
                const int m = r0 + half*8;
                float2 o;
                o.x = (acc[ma][na][half*2+0] + bx) * scale;
                o.y = (acc[ma][na][half*2+1] + by) * scale;
                if (shaped) {
                    int b = m >> 11, s = m & (SS-1);
                    int h = c0 >> 6, dh = c0 & 63;
                    *(float2*)&C[(((size_t)b*HH + h)*SS + s)*DHH + dh] = o;
                } else {
                    *(float2*)&C[(size_t)m * DD + c0] = o;
                }
            }
        }
    }
}

// ---------------------------------------------------------------------------
// Fused flash attention: per CTA 128 q rows x one bh. 8 warps x 16 rows.
// S = 3-term split-bf16 MMA; online softmax; PV = 3-term split-bf16 MMA.
// ---------------------------------------------------------------------------
#define RSK 72
#define RSV 136
#define KTILE_B (128*RSK*2)               // 18432
#define VTILE_B (64*RSV*2)                // 17408
#define OFF_K   (2*KTILE_B)               // Q hi+lo occupy [0, 2*KTILE_B)
#define OFF_V   (OFF_K + 4*KTILE_B)
#define FSMEM   (OFF_V + 4*VTILE_B)       // 180224

__global__ __launch_bounds__(256, 1) void flash_kernel(
    const __nv_bfloat16* __restrict__ qh, const __nv_bfloat16* __restrict__ ql,
    const __nv_bfloat16* __restrict__ kh, const __nv_bfloat16* __restrict__ kl,
    const __nv_bfloat16* __restrict__ vh, const __nv_bfloat16* __restrict__ vl,
    const char* __restrict__ mask, float* __restrict__ ctx)
{
    extern __shared__ char smem[];
    const int tid = threadIdx.x, wid = tid >> 5, lane = tid & 31;
    const int bh = blockIdx.y, q0 = blockIdx.x * 128;
    const int b = bh >> 4, h = bh & 15;
    const int mode = g_maskmode;

    const __nv_bfloat16* qhb = qh + ((size_t)bh*SS + q0) * DHH;
    const __nv_bfloat16* qlb = ql + ((size_t)bh*SS + q0) * DHH;
    const __nv_bfloat16* khb = kh + (size_t)bh*SS*DHH;
    const __nv_bfloat16* klb = kl + (size_t)bh*SS*DHH;
    const __nv_bfloat16* vhb = vh + (size_t)bh*DHH*SS;
    const __nv_bfloat16* vlb = vl + (size_t)bh*DHH*SS;

    // Q tiles (hi, lo) -> smem, group 0
    {
        const __nv_bfloat16* s2[2] = { qhb, qlb };
#pragma unroll
        for (int t = 0; t < 2; t++) {
            char* dst = smem + t * KTILE_B;
#pragma unroll
            for (int it = 0; it < 4; it++) {
                int i = tid + it*256;
                int r = i >> 3, seg = i & 7;
                cp_async16(smem_u32(dst + (r*RSK + seg*8)*2), s2[t] + (size_t)r*DHH + seg*8);
            }
        }
        cp_commit();
    }

    auto load_kv = [&](int kt, int buf) {
        char* dk = smem + OFF_K + buf * (2*KTILE_B);
#pragma unroll
        for (int it = 0; it < 4; it++) {
            int i = tid + it*256;
            int r = i >> 3, seg = i & 7;
            cp_async16(smem_u32(dk + (r*RSK + seg*8)*2),
                       khb + ((size_t)(kt*128 + r))*DHH + seg*8);
        }
        dk += KTILE_B;
#pragma unroll
        for (int it = 0; it < 4; it++) {
            int i = tid + it*256;
            int r = i >> 3, seg = i & 7;
            cp_async16(smem_u32(dk + (r*RSK + seg*8)*2),
                       klb + ((size_t)(kt*128 + r))*DHH + seg*8);
        }
        char* dv = smem + OFF_V + buf * (2*VTILE_B);
#pragma unroll
        for (int it = 0; it < 4; it++) {
            int i = tid + it*256;
            int r = i >> 4, seg = i & 15;
            cp_async16(smem_u32(dv + (r*RSV + seg*8)*2),
                       vhb + (size_t)r*SS + kt*128 + seg*8);
        }
        dv += VTILE_B;
#pragma unroll
        for (int it = 0; it < 4; it++) {
            int i = tid + it*256;
            int r = i >> 4, seg = i & 15;
            cp_async16(smem_u32(dv + (r*RSV + seg*8)*2),
                       vlb + (size_t)r*SS + kt*128 + seg*8);
        }
        cp_commit();
    };

    load_kv(0, 0);          // group 1
    cp_wait<1>();           // Q (group 0) complete
    __syncthreads();

    // Q fragments
    uint32_t aqh[4][4], aql[4][4];
    {
        const int lr = lane & 15, ch = (lane >> 4) << 3;
        const uint32_t qHiB = smem_u32(smem), qLoB = qHiB + KTILE_B;
#pragma unroll
        for (int ks = 0; ks < 4; ks++) {
            uint32_t off = ((wid*16 + lr)*RSK + ks*16 + ch)*2;
            ldm_x4(aqh[ks], qHiB + off);
            ldm_x4(aql[ks], qLoB + off);
        }
    }

    const int g = lane >> 2, tg = lane & 3;
    const int r0 = q0 + wid*16 + g;
    const int r1 = r0 + 8;
    const int within = lane & 15;
    const int brow = ((lane >> 4) << 3) + (within & 7);
    const int bcolh = (within >> 3) << 3;

    float m0 = -3.4e38f, m1 = -3.4e38f, l0 = 0.f, l1 = 0.f;
    float acco[8][4] = {};

    for (int kt = 0; kt < 16; kt++) {
        const int buf = kt & 1;
        if (kt < 15) { load_kv(kt + 1, buf ^ 1); cp_wait<1>(); }
        else         { cp_wait<0>(); }
        __syncthreads();

        const uint32_t kHiB = smem_u32(smem + OFF_K + buf*2*KTILE_B);
        const uint32_t kLoB = kHiB + KTILE_B;
        const uint32_t vHiB = smem_u32(smem + OFF_V + buf*2*VTILE_B);
        const uint32_t vLoB = vHiB + VTILE_B;

        // ---- S = Q K^T (3-term) ----
        float accs[16][4];
#pragma unroll
        for (int i = 0; i < 16; i++) { accs[i][0]=0.f; accs[i][1]=0.f; accs[i][2]=0.f; accs[i][3]=0.f; }

#pragma unroll
        for (int np = 0; np < 8; np++) {
#pragma unroll
            for (int ks = 0; ks < 4; ks++) {
                uint32_t bh4[4], bl4[4];
                uint32_t off = ((np*16 + brow)*RSK + ks*16 + bcolh)*2;
                ldm_x4(bh4, kHiB + off);
                ldm_x4(bl4, kLoB + off);
                mma_bf16(accs[2*np],   aqh[ks], bh4);
                mma_bf16(accs[2*np],   aqh[ks], bl4);
                mma_bf16(accs[2*np],   aql[ks], bh4);
                mma_bf16(accs[2*np+1], aqh[ks], bh4+2);
                mma_bf16(accs[2*np+1], aqh[ks], bl4+2);
                mma_bf16(accs[2*np+1], aql[ks], bh4+2);
            }
        }

        // ---- mask select ----
        const int kc0 = kt*128 + tg*2;
        if (mode) {
            const int* mb0 = (const int*)mask + ((size_t)b*SS + r0)*SS;
            const int* mb1 = (const int*)mask + ((size_t)b*SS + r1)*SS;
#pragma unroll
            for (int na = 0; na < 16; na++) {
                int c = kc0 + na*8;
                int2 mq0 = *(const int2*)(mb0 + c);
                int2 mq1 = *(const int2*)(mb1 + c);
                if (mq0.x) accs[na][0] = -1e18f;
                if (mq0.y) accs[na][1] = -1e18f;
                if (mq1.x) accs[na][2] = -1e18f;
                if (mq1.y) accs[na][3] = -1e18f;
            }
        } else {
            const unsigned char* mb0 = (const unsigned char*)mask + ((size_t)b*SS + r0)*SS;
            const unsigned char* mb1 = (const unsigned char*)mask + ((size_t)b*SS + r1)*SS;
#pragma unroll
            for (int na = 0; na < 16; na++) {
                int c = kc0 + na*8;
                if (mb0[c])   accs[na][0] = -1e18f;
                if (mb0[c+1]) accs[na][1] = -1e18f;
                if (mb1[c])   accs[na][2] = -1e18f;
                if (mb1[c+1]) accs[na][3] = -1e18f;
            }
        }

        // ---- online softmax ----
        float mr0 = -3.4e38f, mr1 = -3.4e38f;
#pragma unroll
        for (int na = 0; na < 16; na++) {
            mr0 = fmaxf(mr0, fmaxf(accs[na][0], accs[na][1]));
            mr1 = fmaxf(mr1, fmaxf(accs[na][2], accs[na][3]));
        }
        mr0 = fmaxf(mr0, __shfl_xor_sync(0xffffffffu, mr0, 1));
        mr0 = fmaxf(mr0, __shfl_xor_sync(0xffffffffu, mr0, 2));
        mr1 = fmaxf(mr1, __shfl_xor_sync(0xffffffffu, mr1, 1));
        mr1 = fmaxf(mr1, __shfl_xor_sync(0xffffffffu, mr1, 2));
        float nm0 = fmaxf(m0, mr0), nm1 = fmaxf(m1, mr1);
        float a0 = __expf(m0 - nm0), a1 = __expf(m1 - nm1);
        m0 = nm0; m1 = nm1;

        float s0 = 0.f, s1 = 0.f;
#pragma unroll
        for (int na = 0; na < 16; na++) {
            accs[na][0] = __expf(accs[na][0] - nm0);
            accs[na][1] = __expf(accs[na][1] - nm0);
            accs[na][2] = __expf(accs[na][2] - nm1);
            accs[na][3] = __expf(accs[na][3] - nm1);
            s0 += accs[na][0] + accs[na][1];
            s1 += accs[na][2] + accs[na][3];
        }
        s0 += __shfl_xor_sync(0xffffffffu, s0, 1);
        s0 += __shfl_xor_sync(0xffffffffu, s0, 2);
        s1 += __shfl_xor_sync(0xffffffffu, s1, 1);
        s1 += __shfl_xor_sync(0xffffffffu, s1, 2);
        l0 = l0*a0 + s0;
        l1 = l1*a1 + s1;
#pragma unroll
        for (int no = 0; no < 8; no++) {
            acco[no][0] *= a0; acco[no][1] *= a0;
            acco[no][2] *= a1; acco[no][3] *= a1;
        }

        // ---- O += P V (3-term), in two k-halves ----
#pragma unroll
        for (int half = 0; half < 2; half++) {
            uint32_t pfh[4][4], pfl[4][4];
#pragma unroll
            for (int j2 = 0; j2 < 4; j2++) {
                int ai = (half*4 + j2)*2;
#pragma unroll
                for (int pq = 0; pq < 2; pq++) {
                    float x0 = accs[ai+pq][0], x1 = accs[ai+pq][1];
                    float y0 = accs[ai+pq][2], y1 = accs[ai+pq][3];
                    __nv_bfloat162 h01 = __floats2bfloat162_rn(x0, x1);
                    __nv_bfloat162 h23 = __floats2bfloat162_rn(y0, y1);
                    float2 f01 = __bfloat1622float2(h01);
                    float2 f23 = __bfloat1622float2(h23);
                    __nv_bfloat162 e01 = __floats2bfloat162_rn(x0 - f01.x, x1 - f01.y);
                    __nv_bfloat162 e23 = __floats2bfloat162_rn(y0 - f23.x, y1 - f23.y);
                    pfh[j2][pq*2+0] = *(uint32_t*)&h01;
                    pfh[j2][pq*2+1] = *(uint32_t*)&h23;
                    pfl[j2][pq*2+0] = *(uint32_t*)&e01;
                    pfl[j2][pq*2+1] = *(uint32_t*)&e23;
                }
            }
#pragma unroll
            for (int nop = 0; nop < 4; nop++) {
#pragma unroll
                for (int j2 = 0; j2 < 4; j2++) {
                    int j = half*4 + j2;
                    uint32_t vb4h[4], vb4l[4];
                    uint32_t off = ((nop*16 + brow)*RSV + j*16 + bcolh)*2;
                    ldm_x4(vb4h, vHiB + off);
                    ldm_x4(vb4l, vLoB + off);
                    mma_bf16(acco[2*nop],   pfh[j2], vb4h);
                    mma_bf16(acco[2*nop],   pfh[j2], vb4l);
                    mma_bf16(acco[2*nop],   pfl[j2], vb4h);
                    mma_bf16(acco[2*nop+1], pfh[j2], vb4h+2);
                    mma_bf16(acco[2*nop+1], pfh[j2], vb4l+2);
                    mma_bf16(acco[2*nop+1], pfl[j2], vb4h+2);
                }
            }
        }
        __syncthreads();
    }

    // ---- epilogue: normalize, write ctx [b][s][h*64+d] ----
    const float inv0 = 1.f / l0, inv1 = 1.f / l1;
    float* c0p = ctx + ((size_t)(b*SS) + r0)*DD + h*DHH;
    float* c1p = ctx + ((size_t)(b*SS) + r1)*DD + h*DHH;
#pragma unroll
    for (int no = 0; no < 8; no++) {
        int c = no*8 + tg*2;
        *(float2*)(c0p + c) = make_float2(acco[no][0]*inv0, acco[no][1]*inv0);
        *(float2*)(c1p + c) = make_float2(acco[no][2]*inv1, acco[no][3]*inv1);
    }
}

// ---------------------------------------------------------------------------
// head-0 scores (SIMT) for the top_attn output
// ---------------------------------------------------------------------------
__global__ __launch_bounds__(256) void scores_h0_kernel(
    const float* __restrict__ q, const float* __restrict__ k,
    const char* __restrict__ mask, float* __restrict__ scores)
{
    __shared__ float Qs[64][68];
    __shared__ float Ks[64][68];
    const int z  = blockIdx.z;         // batch
    const int bh = z * HH;             // head 0
    const int qi0 = blockIdx.y * 64;
    const int ki0 = blockIdx.x * 64;
    const float* qb = q + (size_t)bh * SS * DHH;
    const float* kb = k + (size_t)bh * SS * DHH;
    const int tid = threadIdx.x;
    const int tx = tid & 15, ty = tid >> 4;
    const int mode = g_maskmode;

#pragma unroll
    for (int it = 0; it < 4; it++) {
        int l = tid + 256*it;
        int r = l >> 4;
        int c = (l & 15) << 2;
        float4 a = *(const float4*)(qb + (size_t)(qi0 + r)*DHH + c);
        Qs[c+0][r]=a.x; Qs[c+1][r]=a.y; Qs[c+2][r]=a.z; Qs[c+3][r]=a.w;
        float4 v = *(const float4*)(kb + (size_t)(ki0 + r)*DHH + c);
        Ks[c+0][r]=v.x; Ks[c+1][r]=v.y; Ks[c+2][r]=v.z; Ks[c+3][r]=v.w;
    }
    __syncthreads();

    float acc[4][4] = {};
#pragma unroll 16
    for (int kk = 0; kk < 64; kk++) {
        float4 ra = *(const float4*)&Qs[kk][ty<<2];
        float4 rb = *(const float4*)&Ks[kk][tx<<2];
        float pa[4] = {ra.x,ra.y,ra.z,ra.w};
        float pb[4] = {rb.x,rb.y,rb.z,rb.w};
#pragma unroll
        for (int i=0;i<4;i++)
#pragma unroll
            for (int j=0;j<4;j++)
                acc[i][j] = fmaf(pa[i], pb[j], acc[i][j]);
    }

    float* sb = scores + (size_t)z * SS * SS;
#pragma unroll
    for (int i=0;i<4;i++) {
        int qi = qi0 + (ty<<2) + i;
#pragma unroll
        for (int j=0;j<4;j++) {
            int ki = ki0 + (tx<<2) + j;
            size_t midx = (size_t)z*SS*SS + (size_t)qi*SS + ki;
            int mval = mode ? ((const int*)mask)[midx]
                            : (int)((const unsigned char*)mask)[midx];
            sb[(size_t)qi*SS + ki] = mval ? -1e18f : acc[i][j];
        }
    }
}

// ---------------------------------------------------------------------------
// head-0 softmax -> top_attn output (read-only source)
// ---------------------------------------------------------------------------
__global__ __launch_bounds__(256) void softmax_h0_kernel(
    const float* __restrict__ scores, float* __restrict__ topattn)
{
    const int r = blockIdx.x;               // b*S + qi
    const float* row = scores + (size_t)r * SS;
    const int tid = threadIdx.x;
    __shared__ float red[256];

    float vals[8];
    float lmax = -3.4e38f;
#pragma unroll
    for (int i=0;i<8;i++) { vals[i] = row[tid + 256*i]; lmax = fmaxf(lmax, vals[i]); }
    red[tid] = lmax; __syncthreads();
    for (int s=128; s>0; s>>=1) { if (tid < s) red[tid] = fmaxf(red[tid], red[tid+s]); __syncthreads(); }
    float m = red[0]; __syncthreads();

    float lsum = 0.f;
#pragma unroll
    for (int i=0;i<8;i++) { vals[i] = __expf(vals[i] - m); lsum += vals[i]; }
    red[tid] = lsum; __syncthreads();
    for (int s=128; s>0; s>>=1) { if (tid < s) red[tid] += red[tid+s]; __syncthreads(); }
    float inv = 1.0f / red[0];

    float* tp = topattn + (size_t)r * SS;
#pragma unroll
    for (int i=0;i<8;i++) tp[tid + 256*i] = vals[i] * inv;
}

// ---------------------------------------------------------------------------
extern "C" void kernel_launch(void* const* d_in, const int* in_sizes, int n_in,
                              void* d_out, int out_size)
{
    const float* key   = (const float*)d_in[0];
    const float* value = (const float*)d_in[1];
    const float* query = (const float*)d_in[2];
    const char*  mask  = (const char*)d_in[3];
    const float* Wk = (const float*)d_in[4];
    const float* bk = (const float*)d_in[5];
    const float* Wv = (const float*)d_in[6];
    const float* bv = (const float*)d_in[7];
    const float* Wq = (const float*)d_in[8];
    const float* bq = (const float*)d_in[9];
    const float* Wo = (const float*)d_in[10];
    const float* bo = (const float*)d_in[11];
    float* out = (float*)d_out;

    float *q, *k, *v, *attn, *ctx;
    cudaGetSymbolAddress((void**)&q,    g_q);
    cudaGetSymbolAddress((void**)&k,    g_k);
    cudaGetSymbolAddress((void**)&v,    g_v);
    cudaGetSymbolAddress((void**)&attn, g_attn);
    cudaGetSymbolAddress((void**)&ctx,  g_ctx);

    __nv_bfloat16 *keyh,*keyl,*valh,*vall,*qryh,*qryl,*ctxh,*ctxl;
    __nv_bfloat16 *wkh,*wkl,*wvh,*wvl,*wqh,*wql,*woh,*wol;
    __nv_bfloat16 *qsh,*qsl,*ksh,*ksl,*vth,*vtl;
    cudaGetSymbolAddress((void**)&keyh, g_key_hi); cudaGetSymbolAddress((void**)&keyl, g_key_lo);
    cudaGetSymbolAddress((void**)&valh, g_val_hi); cudaGetSymbolAddress((void**)&vall, g_val_lo);
    cudaGetSymbolAddress((void**)&qryh, g_qry_hi); cudaGetSymbolAddress((void**)&qryl, g_qry_lo);
    cudaGetSymbolAddress((void**)&ctxh, g_ctx_hi); cudaGetSymbolAddress((void**)&ctxl, g_ctx_lo);
    cudaGetSymbolAddress((void**)&wkh,  g_wk_hi);  cudaGetSymbolAddress((void**)&wkl,  g_wk_lo);
    cudaGetSymbolAddress((void**)&wvh,  g_wv_hi);  cudaGetSymbolAddress((void**)&wvl,  g_wv_lo);
    cudaGetSymbolAddress((void**)&wqh,  g_wq_hi);  cudaGetSymbolAddress((void**)&wql,  g_wq_lo);
    cudaGetSymbolAddress((void**)&woh,  g_wo_hi);  cudaGetSymbolAddress((void**)&wol,  g_wo_lo);
    cudaGetSymbolAddress((void**)&qsh,  g_qs_hi);  cudaGetSymbolAddress((void**)&qsl,  g_qs_lo);
    cudaGetSymbolAddress((void**)&ksh,  g_ks_hi);  cudaGetSymbolAddress((void**)&ksl,  g_ks_lo);
    cudaGetSymbolAddress((void**)&vth,  g_vt_hi);  cudaGetSymbolAddress((void**)&vtl,  g_vt_lo);

    cudaFuncSetAttribute(gemm_mma, cudaFuncAttributeMaxDynamicSharedMemorySize, GSMEM);
    cudaFuncSetAttribute(flash_kernel, cudaFuncAttributeMaxDynamicSharedMemorySize, FSMEM);

    detect_mask_kernel<<<1, 256>>>((const unsigned int*)mask);

    const int nIn4 = MM*DD/4, nW4 = DD*DD/4;
    split_kernel<<<nIn4/256, 256>>>(key,   keyh, keyl, nIn4);
    split_kernel<<<nIn4/256, 256>>>(value, valh, vall, nIn4);
    split_kernel<<<nIn4/256, 256>>>(query, qryh, qryl, nIn4);
    split_kernel<<<nW4/256, 256>>>(Wk, wkh, wkl, nW4);
    split_kernel<<<nW4/256, 256>>>(Wv, wvh, wvl, nW4);
    split_kernel<<<nW4/256, 256>>>(Wq, wqh, wql, nW4);
    split_kernel<<<nW4/256, 256>>>(Wo, woh, wol, nW4);

    dim3 gtc(DD/128, MM/128);   // (8, 32)
    gemm_mma<<<gtc, 256, GSMEM>>>(keyh, keyl, wkh, wkl, bk, k, 1.0f,   1);
    gemm_mma<<<gtc, 256, GSMEM>>>(valh, vall, wvh, wvl, bv, v, 1.0f,   1);
    gemm_mma<<<gtc, 256, GSMEM>>>(qryh, qryl, wqh, wql, bq, q, 0.125f, 1);

    // attention operand prep
    split_kernel<<<nIn4/256, 256>>>(q, qsh, qsl, nIn4);
    split_kernel<<<nIn4/256, 256>>>(k, ksh, ksl, nIn4);
    vt_split_kernel<<<dim3(SS/64, BHH), 256>>>(v, vth, vtl);

    // head-0 probs for top_attn output
    scores_h0_kernel<<<dim3(SS/64, SS/64, BB), 256>>>(q, k, mask, attn);
    softmax_h0_kernel<<<BB*SS, 256>>>(attn, out + (size_t)MM*DD);

    // fused attention -> ctx
    flash_kernel<<<dim3(SS/128, BHH), 256, FSMEM>>>(qsh, qsl, ksh, ksl, vth, vtl, mask, ctx);

    // output projection
    split_kernel<<<nIn4/256, 256>>>(ctx, ctxh, ctxl, nIn4);
    gemm_mma<<<gtc, 256, GSMEM>>>(ctxh, ctxl, woh, wol, bo, out, 1.0f, 0);
}

// round 6
// speedup vs baseline: 2.9034x; 1.0391x over previous
#include <cuda_runtime.h>
#include <cuda_bf16.h>
#include <cstdint>

// Problem constants
#define BB  2
#define SS  2048
#define DD  1024
#define HH  16
#define DHH 64
#define MM  (BB*SS)    // 4096
#define BHH (BB*HH)    // 32

// ---------------------------------------------------------------------------
// Scratch (device globals)
// ---------------------------------------------------------------------------
__device__ float g_attn[(size_t)BB*SS*SS];     // head-0 scores (32MB)
__device__ int   g_maskmode;

__device__ __nv_bfloat16 g_key_hi[(size_t)MM*DD],  g_key_lo[(size_t)MM*DD];
__device__ __nv_bfloat16 g_val_hi[(size_t)MM*DD],  g_val_lo[(size_t)MM*DD];
__device__ __nv_bfloat16 g_qry_hi[(size_t)MM*DD],  g_qry_lo[(size_t)MM*DD];
__device__ __nv_bfloat16 g_ctx_hi[(size_t)MM*DD],  g_ctx_lo[(size_t)MM*DD];
__device__ __nv_bfloat16 g_wk_hi[(size_t)DD*DD],   g_wk_lo[(size_t)DD*DD];
__device__ __nv_bfloat16 g_wv_hi[(size_t)DD*DD],   g_wv_lo[(size_t)DD*DD];
__device__ __nv_bfloat16 g_wq_hi[(size_t)DD*DD],   g_wq_lo[(size_t)DD*DD];
__device__ __nv_bfloat16 g_wo_hi[(size_t)DD*DD],   g_wo_lo[(size_t)DD*DD];
// attention operands (produced by gemm epilogues)
__device__ __nv_bfloat16 g_qs_hi[(size_t)BHH*SS*DHH], g_qs_lo[(size_t)BHH*SS*DHH];
__device__ __nv_bfloat16 g_ks_hi[(size_t)BHH*SS*DHH], g_ks_lo[(size_t)BHH*SS*DHH];
__device__ __nv_bfloat16 g_vt_hi[(size_t)BHH*DHH*SS], g_vt_lo[(size_t)BHH*DHH*SS]; // [bh][d][s]

// ---------------------------------------------------------------------------
// PTX helpers
// ---------------------------------------------------------------------------
__device__ __forceinline__ uint32_t smem_u32(const void* p) {
    uint32_t a;
    asm("{ .reg .u64 t; cvta.to.shared.u64 t, %1; cvt.u32.u64 %0, t; }" : "=r"(a) : "l"(p));
    return a;
}
__device__ __forceinline__ void cp_async16(uint32_t saddr, const void* gaddr) {
    asm volatile("cp.async.cg.shared.global [%0], [%1], 16;" :: "r"(saddr), "l"(gaddr));
}
__device__ __forceinline__ void cp_commit() { asm volatile("cp.async.commit_group;"); }
template <int N>
__device__ __forceinline__ void cp_wait() { asm volatile("cp.async.wait_group %0;" :: "n"(N)); }

__device__ __forceinline__ void ldm_x4(uint32_t* r, uint32_t addr) {
    asm volatile("ldmatrix.sync.aligned.m8n8.x4.shared.b16 {%0,%1,%2,%3}, [%4];"
        : "=r"(r[0]), "=r"(r[1]), "=r"(r[2]), "=r"(r[3]) : "r"(addr));
}
__device__ __forceinline__ void ldm_x2(uint32_t* r, uint32_t addr) {
    asm volatile("ldmatrix.sync.aligned.m8n8.x2.shared.b16 {%0,%1}, [%2];"
        : "=r"(r[0]), "=r"(r[1]) : "r"(addr));
}
__device__ __forceinline__ void mma_bf16(float* c, const uint32_t* a, const uint32_t* b) {
    asm volatile("mma.sync.aligned.m16n8k16.row.col.f32.bf16.bf16.f32 "
        "{%0,%1,%2,%3}, {%4,%5,%6,%7}, {%8,%9}, {%0,%1,%2,%3};"
        : "+f"(c[0]), "+f"(c[1]), "+f"(c[2]), "+f"(c[3])
        : "r"(a[0]), "r"(a[1]), "r"(a[2]), "r"(a[3]), "r"(b[0]), "r"(b[1]));
}
// split pair of fp32 into bf16x2 hi + bf16x2 lo (packed u32)
__device__ __forceinline__ void split2(float x0, float x1, uint32_t& h, uint32_t& l) {
    __nv_bfloat162 hh = __floats2bfloat162_rn(x0, x1);
    float2 f = __bfloat1622float2(hh);
    __nv_bfloat162 ll = __floats2bfloat162_rn(x0 - f.x, x1 - f.y);
    h = *(uint32_t*)&hh;
    l = *(uint32_t*)&ll;
}

// ---------------------------------------------------------------------------
// Batched splits: inputs (key,value,query) and weights (Wk,Wv,Wq,Wo)
// ---------------------------------------------------------------------------
__global__ __launch_bounds__(256) void split3_kernel(
    const float* __restrict__ x0, const float* __restrict__ x1, const float* __restrict__ x2,
    __nv_bfloat16* __restrict__ h0d, __nv_bfloat16* __restrict__ h1d, __nv_bfloat16* __restrict__ h2d,
    __nv_bfloat16* __restrict__ l0d, __nv_bfloat16* __restrict__ l1d, __nv_bfloat16* __restrict__ l2d)
{
    const int which = blockIdx.y;
    const float* x = which == 0 ? x0 : which == 1 ? x1 : x2;
    __nv_bfloat16* hi = which == 0 ? h0d : which == 1 ? h1d : h2d;
    __nv_bfloat16* lo = which == 0 ? l0d : which == 1 ? l1d : l2d;
    int i = blockIdx.x * 256 + threadIdx.x;
    float4 f = ((const float4*)x)[i];
    uint32_t ha, hb, la, lb;
    split2(f.x, f.y, ha, la);
    split2(f.z, f.w, hb, lb);
    ((uint32_t*)hi)[2*i] = ha; ((uint32_t*)hi)[2*i+1] = hb;
    ((uint32_t*)lo)[2*i] = la; ((uint32_t*)lo)[2*i+1] = lb;
}
__global__ __launch_bounds__(256) void split4_kernel(
    const float* __restrict__ x0, const float* __restrict__ x1,
    const float* __restrict__ x2, const float* __restrict__ x3,
    __nv_bfloat16* __restrict__ h0d, __nv_bfloat16* __restrict__ h1d,
    __nv_bfloat16* __restrict__ h2d, __nv_bfloat16* __restrict__ h3d,
    __nv_bfloat16* __restrict__ l0d, __nv_bfloat16* __restrict__ l1d,
    __nv_bfloat16* __restrict__ l2d, __nv_bfloat16* __restrict__ l3d)
{
    const int which = blockIdx.y;
    const float* x = which == 0 ? x0 : which == 1 ? x1 : which == 2 ? x2 : x3;
    __nv_bfloat16* hi = which == 0 ? h0d : which == 1 ? h1d : which == 2 ? h2d : h3d;
    __nv_bfloat16* lo = which == 0 ? l0d : which == 1 ? l1d : which == 2 ? l2d : l3d;
    int i = blockIdx.x * 256 + threadIdx.x;
    float4 f = ((const float4*)x)[i];
    uint32_t ha, hb, la, lb;
    split2(f.x, f.y, ha, la);
    split2(f.z, f.w, hb, lb);
    ((uint32_t*)hi)[2*i] = ha; ((uint32_t*)hi)[2*i+1] = hb;
    ((uint32_t*)lo)[2*i] = la; ((uint32_t*)lo)[2*i+1] = lb;
}

// ---------------------------------------------------------------------------
// Mask dtype detection
// ---------------------------------------------------------------------------
__global__ void detect_mask_kernel(const unsigned int* __restrict__ m) {
    __shared__ int bad;
    if (threadIdx.x == 0) bad = 0;
    __syncthreads();
    int local = 0;
    for (int i = threadIdx.x; i < 8192; i += 256)
        if (m[i] > 1u) local = 1;
    if (local) atomicOr(&bad, 1);
    __syncthreads();
    if (threadIdx.x == 0) g_maskmode = bad ? 0 : 1;
}

// ---------------------------------------------------------------------------
// mma.sync split-bf16 GEMM.
// mode 0: C fp32 [m][n]
// mode 1: Chi/Clo bf16 shaped [b][h][s][dh]
// mode 2: Chi/Clo bf16 transposed V [bh][d][s] (smem-staged transpose)
// ---------------------------------------------------------------------------
#define RS 40
#define TILE_B (128*RS*2)
#define BUF_B  (4*TILE_B)
#define GSMEM  (2*BUF_B)     // 81920 (also covers mode-2 staging: 128*133*4)

__global__ __launch_bounds__(256) void gemm_mma(
    const __nv_bfloat16* __restrict__ Ahi, const __nv_bfloat16* __restrict__ Alo,
    const __nv_bfloat16* __restrict__ Whi, const __nv_bfloat16* __restrict__ Wlo,
    const float* __restrict__ bias, float* __restrict__ C,
    __nv_bfloat16* __restrict__ Chi, __nv_bfloat16* __restrict__ Clo,
    float scale, int mode)
{
    extern __shared__ char smem[];
    const int tid  = threadIdx.x;
    const int wid  = tid >> 5, lane = tid & 31;
    const int warp_m = wid & 1, warp_n = wid >> 1;
    const int m0 = blockIdx.y * 128, n0 = blockIdx.x * 128;

    const __nv_bfloat16* srcs[4] = {
        Ahi + (size_t)m0 * DD, Alo + (size_t)m0 * DD,
        Whi + (size_t)n0 * DD, Wlo + (size_t)n0 * DD };

    auto load_chunk = [&](int chunk, int buf) {
        char* sb = smem + buf * BUF_B;
#pragma unroll
        for (int t = 0; t < 4; t++) {
            const __nv_bfloat16* src = srcs[t] + chunk * 32;
            char* dst = sb + t * TILE_B;
#pragma unroll
            for (int it = 0; it < 2; it++) {
                int i = tid + 256 * it;
                int r = i >> 2, seg = i & 3;
                cp_async16(smem_u32(dst + r * (RS*2) + seg * 16),
                           src + (size_t)r * DD + seg * 8);
            }
        }
        cp_commit();
    };

    float acc[4][4][4] = {};

    load_chunk(0, 0);
    for (int chunk = 0; chunk < 32; chunk++) {
        const int buf = chunk & 1;
        if (chunk + 1 < 32) { load_chunk(chunk + 1, buf ^ 1); cp_wait<1>(); }
        else                { cp_wait<0>(); }
        __syncthreads();

        char* sb = smem + buf * BUF_B;
        const uint32_t aHiB = smem_u32(sb);
        const uint32_t aLoB = aHiB + TILE_B;
        const uint32_t bHiB = aHiB + 2*TILE_B;
        const uint32_t bLoB = aHiB + 3*TILE_B;

#pragma unroll
        for (int ks = 0; ks < 2; ks++) {
            const int k0 = ks * 16;
            uint32_t ahi[4][4], alo[4][4], bhi[4][2], blo[4][2];
            {
                const int lr = lane & 15;
                const int ch = (lane >> 4) << 3;
#pragma unroll
                for (int ma = 0; ma < 4; ma++) {
                    uint32_t off = ((warp_m*64 + ma*16 + lr) * RS + k0 + ch) * 2;
                    ldm_x4(ahi[ma], aHiB + off);
                    ldm_x4(alo[ma], aLoB + off);
                }
            }
            {
                const int idx = lane & 15;
                const int nr = idx & 7;
                const int kh = (idx >> 3) << 3;
#pragma unroll
                for (int na = 0; na < 4; na++) {
                    uint32_t off = ((warp_n*32 + na*8 + nr) * RS + k0 + kh) * 2;
                    ldm_x2(bhi[na], bHiB + off);
                    ldm_x2(blo[na], bLoB + off);
                }
            }
#pragma unroll
            for (int ma = 0; ma < 4; ma++)
#pragma unroll
                for (int na = 0; na < 4; na++) {
                    mma_bf16(acc[ma][na], ahi[ma], bhi[na]);
                    mma_bf16(acc[ma][na], ahi[ma], blo[na]);
                    mma_bf16(acc[ma][na], alo[ma], bhi[na]);
                }
        }
        __syncthreads();
    }

    if (mode == 2) {
        // stage bias-added fp32 tile into smem, then transposed split write
        float* ts = (float*)smem;                  // [128][133]
#pragma unroll
        for (int ma = 0; ma < 4; ma++) {
            const int rl = warp_m*64 + ma*16 + (lane >> 2);
#pragma unroll
            for (int na = 0; na < 4; na++) {
                const int cl = warp_n*32 + na*8 + (lane & 3)*2;
                const float bx = bias[n0 + cl], by = bias[n0 + cl + 1];
#pragma unroll
                for (int half = 0; half < 2; half++) {
                    ts[(rl + half*8)*133 + cl]     = acc[ma][na][half*2+0] + bx;
                    ts[(rl + half*8)*133 + cl + 1] = acc[ma][na][half*2+1] + by;
                }
            }
        }
        __syncthreads();
        const int b = m0 >> 11, s0 = m0 & (SS-1);
        const int nl = tid >> 1;                   // 0..127
        const int soff = (tid & 1) * 64;
        const int n = n0 + nl;
        const int h = n >> 6, dh = n & 63;
        __nv_bfloat16* vh = Chi + (((size_t)(b*HH + h))*DHH + dh)*SS + s0 + soff;
        __nv_bfloat16* vl = Clo + (((size_t)(b*HH + h))*DHH + dh)*SS + s0 + soff;
#pragma unroll
        for (int s = 0; s < 64; s += 2) {
            float x0 = ts[(soff + s)*133 + nl];
            float x1 = ts[(soff + s + 1)*133 + nl];
            uint32_t hp, lp;
            split2(x0, x1, hp, lp);
            *(uint32_t*)(vh + s) = hp;
            *(uint32_t*)(vl + s) = lp;
        }
        return;
    }

#pragma unroll
    for (int ma = 0; ma < 4; ma++) {
        const int r0 = m0 + warp_m*64 + ma*16 + (lane >> 2);
#pragma unroll
        for (int na = 0; na < 4; na++) {
            const int c0 = n0 + warp_n*32 + na*8 + (lane & 3)*2;
            const float bx = bias[c0], by = bias[c0+1];
#pragma unroll
            for (int half = 0; half < 2; half++) {
                const int m = r0 + half*8;
                float x0 = (acc[ma][na][half*2+0] + bx) * scale;
                float x1 = (acc[ma][na][half*2+1] + by) * scale;
                if (mode == 1) {
                    int b = m >> 11, s = m & (SS-1);
                    int h = c0 >> 6, dh = c0 & 63;
                    size_t o = (((size_t)b*HH + h)*SS + s)*DHH + dh;
                    uint32_t hp, lp;
                    split2(x0, x1, hp, lp);
                    *(uint32_t*)(Chi + o) = hp;
                    *(uint32_t*)(Clo + o) = lp;
                } else {
                    *(float2*)&C[(size_t)m * DD + c0] = make_float2(x0, x1);
                }
            }
        }
    }
}

// ---------------------------------------------------------------------------
// Fused flash attention -> ctx bf16 hi/lo
// ---------------------------------------------------------------------------
#define RSK 72
#define RSV 136
#define KTILE_B (128*RSK*2)
#define VTILE_B (64*RSV*2)
#define OFF_K   (2*KTILE_B)
#define OFF_V   (OFF_K + 4*KTILE_B)
#define FSMEM   (OFF_V + 4*VTILE_B)

__global__ __launch_bounds__(256, 1) void flash_kernel(
    const __nv_bfloat16* __restrict__ qh, const __nv_bfloat16* __restrict__ ql,
    const __nv_bfloat16* __restrict__ kh, const __nv_bfloat16* __restrict__ kl,
    const __nv_bfloat16* __restrict__ vh, const __nv_bfloat16* __restrict__ vl,
    const char* __restrict__ mask,
    __nv_bfloat16* __restrict__ ctxh, __nv_bfloat16* __restrict__ ctxl)
{
    extern __shared__ char smem[];
    const int tid = threadIdx.x, wid = tid >> 5, lane = tid & 31;
    const int bh = blockIdx.y, q0 = blockIdx.x * 128;
    const int b = bh >> 4, h = bh & 15;
    const int mode = g_maskmode;

    const __nv_bfloat16* qhb = qh + ((size_t)bh*SS + q0) * DHH;
    const __nv_bfloat16* qlb = ql + ((size_t)bh*SS + q0) * DHH;
    const __nv_bfloat16* khb = kh + (size_t)bh*SS*DHH;
    const __nv_bfloat16* klb = kl + (size_t)bh*SS*DHH;
    const __nv_bfloat16* vhb = vh + (size_t)bh*DHH*SS;
    const __nv_bfloat16* vlb = vl + (size_t)bh*DHH*SS;

    {
        const __nv_bfloat16* s2[2] = { qhb, qlb };
#pragma unroll
        for (int t = 0; t < 2; t++) {
            char* dst = smem + t * KTILE_B;
#pragma unroll
            for (int it = 0; it < 4; it++) {
                int i = tid + it*256;
                int r = i >> 3, seg = i & 7;
                cp_async16(smem_u32(dst + (r*RSK + seg*8)*2), s2[t] + (size_t)r*DHH + seg*8);
            }
        }
        cp_commit();
    }

    auto load_kv = [&](int kt, int buf) {
        char* dk = smem + OFF_K + buf * (2*KTILE_B);
#pragma unroll
        for (int it = 0; it < 4; it++) {
            int i = tid + it*256;
            int r = i >> 3, seg = i & 7;
            cp_async16(smem_u32(dk + (r*RSK + seg*8)*2),
                       khb + ((size_t)(kt*128 + r))*DHH + seg*8);
        }
        dk += KTILE_B;
#pragma unroll
        for (int it = 0; it < 4; it++) {
            int i = tid + it*256;
            int r = i >> 3, seg = i & 7;
            cp_async16(smem_u32(dk + (r*RSK + seg*8)*2),
                       klb + ((size_t)(kt*128 + r))*DHH + seg*8);
        }
        char* dv = smem + OFF_V + buf * (2*VTILE_B);
#pragma unroll
        for (int it = 0; it < 4; it++) {
            int i = tid + it*256;
            int r = i >> 4, seg = i & 15;
            cp_async16(smem_u32(dv + (r*RSV + seg*8)*2),
                       vhb + (size_t)r*SS + kt*128 + seg*8);
        }
        dv += VTILE_B;
#pragma unroll
        for (int it = 0; it < 4; it++) {
            int i = tid + it*256;
            int r = i >> 4, seg = i & 15;
            cp_async16(smem_u32(dv + (r*RSV + seg*8)*2),
                       vlb + (size_t)r*SS + kt*128 + seg*8);
        }
        cp_commit();
    };

    load_kv(0, 0);
    cp_wait<1>();
    __syncthreads();

    uint32_t aqh[4][4], aql[4][4];
    {
        const int lr = lane & 15, ch = (lane >> 4) << 3;
        const uint32_t qHiB = smem_u32(smem), qLoB = qHiB + KTILE_B;
#pragma unroll
        for (int ks = 0; ks < 4; ks++) {
            uint32_t off = ((wid*16 + lr)*RSK + ks*16 + ch)*2;
            ldm_x4(aqh[ks], qHiB + off);
            ldm_x4(aql[ks], qLoB + off);
        }
    }

    const int g = lane >> 2, tg = lane & 3;
    const int r0 = q0 + wid*16 + g;
    const int r1 = r0 + 8;
    const int within = lane & 15;
    const int brow = ((lane >> 4) << 3) + (within & 7);
    const int bcolh = (within >> 3) << 3;

    float m0 = -3.4e38f, m1 = -3.4e38f, l0 = 0.f, l1 = 0.f;
    float acco[8][4] = {};

    for (int kt = 0; kt < 16; kt++) {
        const int buf = kt & 1;
        if (kt < 15) { load_kv(kt + 1, buf ^ 1); cp_wait<1>(); }
        else         { cp_wait<0>(); }
        __syncthreads();

        const uint32_t kHiB = smem_u32(smem + OFF_K + buf*2*KTILE_B);
        const uint32_t kLoB = kHiB + KTILE_B;
        const uint32_t vHiB = smem_u32(smem + OFF_V + buf*2*VTILE_B);
        const uint32_t vLoB = vHiB + VTILE_B;

        float accs[16][4];
#pragma unroll
        for (int i = 0; i < 16; i++) { accs[i][0]=0.f; accs[i][1]=0.f; accs[i][2]=0.f; accs[i][3]=0.f; }

#pragma unroll
        for (int np = 0; np < 8; np++) {
#pragma unroll
            for (int ks = 0; ks < 4; ks++) {
                uint32_t bh4[4], bl4[4];
                uint32_t off = ((np*16 + brow)*RSK + ks*16 + bcolh)*2;
                ldm_x4(bh4, kHiB + off);
                ldm_x4(bl4, kLoB + off);
                mma_bf16(accs[2*np],   aqh[ks], bh4);
                mma_bf16(accs[2*np],   aqh[ks], bl4);
                mma_bf16(accs[2*np],   aql[ks], bh4);
                mma_bf16(accs[2*np+1], aqh[ks], bh4+2);
                mma_bf16(accs[2*np+1], aqh[ks], bl4+2);
                mma_bf16(accs[2*np+1], aql[ks], bh4+2);
            }
        }

        const int kc0 = kt*128 + tg*2;
        if (mode) {
            const int* mb0 = (const int*)mask + ((size_t)b*SS + r0)*SS;
            const int* mb1 = (const int*)mask + ((size_t)b*SS + r1)*SS;
#pragma unroll
            for (int na = 0; na < 16; na++) {
                int c = kc0 + na*8;
                int2 mq0 = *(const int2*)(mb0 + c);
                int2 mq1 = *(const int2*)(mb1 + c);
                if (mq0.x) accs[na][0] = -1e18f;
                if (mq0.y) accs[na][1] = -1e18f;
                if (mq1.x) accs[na][2] = -1e18f;
                if (mq1.y) accs[na][3] = -1e18f;
            }
        } else {
            const unsigned char* mb0 = (const unsigned char*)mask + ((size_t)b*SS + r0)*SS;
            const unsigned char* mb1 = (const unsigned char*)mask + ((size_t)b*SS + r1)*SS;
#pragma unroll
            for (int na = 0; na < 16; na++) {
                int c = kc0 + na*8;
                if (mb0[c])   accs[na][0] = -1e18f;
                if (mb0[c+1]) accs[na][1] = -1e18f;
                if (mb1[c])   accs[na][2] = -1e18f;
                if (mb1[c+1]) accs[na][3] = -1e18f;
            }
        }

        float mr0 = -3.4e38f, mr1 = -3.4e38f;
#pragma unroll
        for (int na = 0; na < 16; na++) {
            mr0 = fmaxf(mr0, fmaxf(accs[na][0], accs[na][1]));
            mr1 = fmaxf(mr1, fmaxf(accs[na][2], accs[na][3]));
        }
        mr0 = fmaxf(mr0, __shfl_xor_sync(0xffffffffu, mr0, 1));
        mr0 = fmaxf(mr0, __shfl_xor_sync(0xffffffffu, mr0, 2));
        mr1 = fmaxf(mr1, __shfl_xor_sync(0xffffffffu, mr1, 1));
        mr1 = fmaxf(mr1, __shfl_xor_sync(0xffffffffu, mr1, 2));
        float nm0 = fmaxf(m0, mr0), nm1 = fmaxf(m1, mr1);
        float a0 = __expf(m0 - nm0), a1 = __expf(m1 - nm1);
        m0 = nm0; m1 = nm1;

        float s0 = 0.f, s1 = 0.f;
#pragma unroll
        for (int na = 0; na < 16; na++) {
            accs[na][0] = __expf(accs[na][0] - nm0);
            accs[na][1] = __expf(accs[na][1] - nm0);
            accs[na][2] = __expf(accs[na][2] - nm1);
            accs[na][3] = __expf(accs[na][3] - nm1);
            s0 += accs[na][0] + accs[na][1];
            s1 += accs[na][2] + accs[na][3];
        }
        s0 += __shfl_xor_sync(0xffffffffu, s0, 1);
        s0 += __shfl_xor_sync(0xffffffffu, s0, 2);
        s1 += __shfl_xor_sync(0xffffffffu, s1, 1);
        s1 += __shfl_xor_sync(0xffffffffu, s1, 2);
        l0 = l0*a0 + s0;
        l1 = l1*a1 + s1;
#pragma unroll
        for (int no = 0; no < 8; no++) {
            acco[no][0] *= a0; acco[no][1] *= a0;
            acco[no][2] *= a1; acco[no][3] *= a1;
        }

#pragma unroll
        for (int half = 0; half < 2; half++) {
            uint32_t pfh[4][4], pfl[4][4];
#pragma unroll
            for (int j2 = 0; j2 < 4; j2++) {
                int ai = (half*4 + j2)*2;
#pragma unroll
                for (int pq = 0; pq < 2; pq++) {
                    split2(accs[ai+pq][0], accs[ai+pq][1], pfh[j2][pq*2+0], pfl[j2][pq*2+0]);
                    split2(accs[ai+pq][2], accs[ai+pq][3], pfh[j2][pq*2+1], pfl[j2][pq*2+1]);
                }
            }
#pragma unroll
            for (int nop = 0; nop < 4; nop++) {
#pragma unroll
                for (int j2 = 0; j2 < 4; j2++) {
                    int j = half*4 + j2;
                    uint32_t vb4h[4], vb4l[4];
                    uint32_t off = ((nop*16 + brow)*RSV + j*16 + bcolh)*2;
                    ldm_x4(vb4h, vHiB + off);
                    ldm_x4(vb4l, vLoB + off);
                    mma_bf16(acco[2*nop],   pfh[j2], vb4h);
                    mma_bf16(acco[2*nop],   pfh[j2], vb4l);
                    mma_bf16(acco[2*nop],   pfl[j2], vb4h);
                    mma_bf16(acco[2*nop+1], pfh[j2], vb4h+2);
                    mma_bf16(acco[2*nop+1], pfh[j2], vb4l+2);
                    mma_bf16(acco[2*nop+1], pfl[j2], vb4h+2);
                }
            }
        }
        __syncthreads();
    }

    // epilogue: normalize, split, write ctx hi/lo [b][s][h*64+d]
    const float inv0 = 1.f / l0, inv1 = 1.f / l1;
    size_t o0 = ((size_t)(b*SS) + r0)*DD + h*DHH;
    size_t o1 = ((size_t)(b*SS) + r1)*DD + h*DHH;
#pragma unroll
    for (int no = 0; no < 8; no++) {
        int c = no*8 + tg*2;
        uint32_t hp, lp;
        split2(acco[no][0]*inv0, acco[no][1]*inv0, hp, lp);
        *(uint32_t*)(ctxh + o0 + c) = hp;
        *(uint32_t*)(ctxl + o0 + c) = lp;
        split2(acco[no][2]*inv1, acco[no][3]*inv1, hp, lp);
        *(uint32_t*)(ctxh + o1 + c) = hp;
        *(uint32_t*)(ctxl + o1 + c) = lp;
    }
}

// ---------------------------------------------------------------------------
// head-0 scores (SIMT) from bf16 hi/lo q,k
// ---------------------------------------------------------------------------
__global__ __launch_bounds__(256) void scores_h0_kernel(
    const __nv_bfloat16* __restrict__ qhp, const __nv_bfloat16* __restrict__ qlp,
    const __nv_bfloat16* __restrict__ khp, const __nv_bfloat16* __restrict__ klp,
    const char* __restrict__ mask, float* __restrict__ scores)
{
    __shared__ float Qs[64][68];
    __shared__ float Ks[64][68];
    const int z  = blockIdx.z;         // batch
    const int bh = z * HH;             // head 0
    const int qi0 = blockIdx.y * 64;
    const int ki0 = blockIdx.x * 64;
    const int tid = threadIdx.x;
    const int tx = tid & 15, ty = tid >> 4;
    const int mode = g_maskmode;
    const size_t qb = ((size_t)bh*SS + qi0)*DHH;
    const size_t kb = ((size_t)bh*SS + ki0)*DHH;

#pragma unroll
    for (int it = 0; it < 4; it++) {
        int l = tid + 256*it;
        int r = l >> 4;
        int c = (l & 15) << 2;
        uint2 qh4 = *(const uint2*)(qhp + qb + (size_t)r*DHH + c);
        uint2 ql4 = *(const uint2*)(qlp + qb + (size_t)r*DHH + c);
        float2 a0 = __bfloat1622float2(*(__nv_bfloat162*)&qh4.x);
        float2 a1 = __bfloat1622float2(*(__nv_bfloat162*)&qh4.y);
        float2 e0 = __bfloat1622float2(*(__nv_bfloat162*)&ql4.x);
        float2 e1 = __bfloat1622float2(*(__nv_bfloat162*)&ql4.y);
        Qs[c+0][r]=a0.x+e0.x; Qs[c+1][r]=a0.y+e0.y; Qs[c+2][r]=a1.x+e1.x; Qs[c+3][r]=a1.y+e1.y;
        uint2 kh4 = *(const uint2*)(khp + kb + (size_t)r*DHH + c);
        uint2 kl4 = *(const uint2*)(klp + kb + (size_t)r*DHH + c);
        a0 = __bfloat1622float2(*(__nv_bfloat162*)&kh4.x);
        a1 = __bfloat1622float2(*(__nv_bfloat162*)&kh4.y);
        e0 = __bfloat1622float2(*(__nv_bfloat162*)&kl4.x);
        e1 = __bfloat1622float2(*(__nv_bfloat162*)&kl4.y);
        Ks[c+0][r]=a0.x+e0.x; Ks[c+1][r]=a0.y+e0.y; Ks[c+2][r]=a1.x+e1.x; Ks[c+3][r]=a1.y+e1.y;
    }
    __syncthreads();

    float acc[4][4] = {};
#pragma unroll 16
    for (int kk = 0; kk < 64; kk++) {
        float4 ra = *(const float4*)&Qs[kk][ty<<2];
        float4 rb = *(const float4*)&Ks[kk][tx<<2];
        float pa[4] = {ra.x,ra.y,ra.z,ra.w};
        float pb[4] = {rb.x,rb.y,rb.z,rb.w};
#pragma unroll
        for (int i=0;i<4;i++)
#pragma unroll
            for (int j=0;j<4;j++)
                acc[i][j] = fmaf(pa[i], pb[j], acc[i][j]);
    }

    float* sb = scores + (size_t)z * SS * SS;
#pragma unroll
    for (int i=0;i<4;i++) {
        int qi = qi0 + (ty<<2) + i;
#pragma unroll
        for (int j=0;j<4;j++) {
            int ki = ki0 + (tx<<2) + j;
            size_t midx = (size_t)z*SS*SS + (size_t)qi*SS + ki;
            int mval = mode ? ((const int*)mask)[midx]
                            : (int)((const unsigned char*)mask)[midx];
            sb[(size_t)qi*SS + ki] = mval ? -1e18f : acc[i][j];
        }
    }
}

// ---------------------------------------------------------------------------
// head-0 softmax -> top_attn output
// ---------------------------------------------------------------------------
__global__ __launch_bounds__(256) void softmax_h0_kernel(
    const float* __restrict__ scores, float* __restrict__ topattn)
{
    const int r = blockIdx.x;
    const float* row = scores + (size_t)r * SS;
    const int tid = threadIdx.x;
    __shared__ float red[256];

    float vals[8];
    float lmax = -3.4e38f;
#pragma unroll
    for (int i=0;i<8;i++) { vals[i] = row[tid + 256*i]; lmax = fmaxf(lmax, vals[i]); }
    red[tid] = lmax; __syncthreads();
    for (int s=128; s>0; s>>=1) { if (tid < s) red[tid] = fmaxf(red[tid], red[tid+s]); __syncthreads(); }
    float m = red[0]; __syncthreads();

    float lsum = 0.f;
#pragma unroll
    for (int i=0;i<8;i++) { vals[i] = __expf(vals[i] - m); lsum += vals[i]; }
    red[tid] = lsum; __syncthreads();
    for (int s=128; s>0; s>>=1) { if (tid < s) red[tid] += red[tid+s]; __syncthreads(); }
    float inv = 1.0f / red[0];

    float* tp = topattn + (size_t)r * SS;
#pragma unroll
    for (int i=0;i<8;i++) tp[tid + 256*i] = vals[i] * inv;
}

// ---------------------------------------------------------------------------
extern "C" void kernel_launch(void* const* d_in, const int* in_sizes, int n_in,
                              void* d_out, int out_size)
{
    const float* key   = (const float*)d_in[0];
    const float* value = (const float*)d_in[1];
    const float* query = (const float*)d_in[2];
    const char*  mask  = (const char*)d_in[3];
    const float* Wk = (const float*)d_in[4];
    const float* bk = (const float*)d_in[5];
    const float* Wv = (const float*)d_in[6];
    const float* bv = (const float*)d_in[7];
    const float* Wq = (const float*)d_in[8];
    const float* bq = (const float*)d_in[9];
    const float* Wo = (const float*)d_in[10];
    const float* bo = (const float*)d_in[11];
    float* out = (float*)d_out;

    float *attn;
    cudaGetSymbolAddress((void**)&attn, g_attn);

    __nv_bfloat16 *keyh,*keyl,*valh,*vall,*qryh,*qryl,*ctxh,*ctxl;
    __nv_bfloat16 *wkh,*wkl,*wvh,*wvl,*wqh,*wql,*woh,*wol;
    __nv_bfloat16 *qsh,*qsl,*ksh,*ksl,*vth,*vtl;
    cudaGetSymbolAddress((void**)&keyh, g_key_hi); cudaGetSymbolAddress((void**)&keyl, g_key_lo);
    cudaGetSymbolAddress((void**)&valh, g_val_hi); cudaGetSymbolAddress((void**)&vall, g_val_lo);
    cudaGetSymbolAddress((void**)&qryh, g_qry_hi); cudaGetSymbolAddress((void**)&qryl, g_qry_lo);
    cudaGetSymbolAddress((void**)&ctxh, g_ctx_hi); cudaGetSymbolAddress((void**)&ctxl, g_ctx_lo);
    cudaGetSymbolAddress((void**)&wkh,  g_wk_hi);  cudaGetSymbolAddress((void**)&wkl,  g_wk_lo);
    cudaGetSymbolAddress((void**)&wvh,  g_wv_hi);  cudaGetSymbolAddress((void**)&wvl,  g_wv_lo);
    cudaGetSymbolAddress((void**)&wqh,  g_wq_hi);  cudaGetSymbolAddress((void**)&wql,  g_wq_lo);
    cudaGetSymbolAddress((void**)&woh,  g_wo_hi);  cudaGetSymbolAddress((void**)&wol,  g_wo_lo);
    cudaGetSymbolAddress((void**)&qsh,  g_qs_hi);  cudaGetSymbolAddress((void**)&qsl,  g_qs_lo);
    cudaGetSymbolAddress((void**)&ksh,  g_ks_hi);  cudaGetSymbolAddress((void**)&ksl,  g_ks_lo);
    cudaGetSymbolAddress((void**)&vth,  g_vt_hi);  cudaGetSymbolAddress((void**)&vtl,  g_vt_lo);

    cudaFuncSetAttribute(gemm_mma, cudaFuncAttributeMaxDynamicSharedMemorySize, GSMEM);
    cudaFuncSetAttribute(flash_kernel, cudaFuncAttributeMaxDynamicSharedMemorySize, FSMEM);

    detect_mask_kernel<<<1, 256>>>((const unsigned int*)mask);

    split3_kernel<<<dim3(MM*DD/4/256, 3), 256>>>(key, value, query,
        keyh, valh, qryh, keyl, vall, qryl);
    split4_kernel<<<dim3(DD*DD/4/256, 4), 256>>>(Wk, Wv, Wq, Wo,
        wkh, wvh, wqh, woh, wkl, wvl, wql, wol);

    dim3 gtc(DD/128, MM/128);   // (8, 32)
    gemm_mma<<<gtc, 256, GSMEM>>>(keyh, keyl, wkh, wkl, bk, nullptr, ksh, ksl, 1.0f,   1);
    gemm_mma<<<gtc, 256, GSMEM>>>(valh, vall, wvh, wvl, bv, nullptr, vth, vtl, 1.0f,   2);
    gemm_mma<<<gtc, 256, GSMEM>>>(qryh, qryl, wqh, wql, bq, nullptr, qsh, qsl, 0.125f, 1);

    // head-0 probs for top_attn output
    scores_h0_kernel<<<dim3(SS/64, SS/64, BB), 256>>>(qsh, qsl, ksh, ksl, mask, attn);
    softmax_h0_kernel<<<BB*SS, 256>>>(attn, out + (size_t)MM*DD);

    // fused attention -> ctx hi/lo
    flash_kernel<<<dim3(SS/128, BHH), 256, FSMEM>>>(qsh, qsl, ksh, ksl, vth, vtl, mask, ctxh, ctxl);

    // output projection
    gemm_mma<<<gtc, 256, GSMEM>>>(ctxh, ctxl, woh, wol, bo, out, nullptr, nullptr, 1.0f, 0);
}